// round 5
// baseline (speedup 1.0000x reference)
#include <cuda_runtime.h>
#include <cuda_bf16.h>
#include <cstdint>

// Problem constants
#define BB 4
#define NN 256
#define EE 63
#define DD 64
#define HH 128

// Exact triangular packing: per b, 256*257/2 = 32896 pairs = 257 tiles of 128.
#define TILES_PER_B 257
#define NTILES (BB * TILES_PER_B)
#define GRID1 152

#define APITCH 136      // bf16 elems per row of p buffer (68 words, conflict-free)
#define W1PITCH 72      // bf16 elems per row of W1
#define IPITCH 144      // bytes per row of s8/u8 tiles (36 words: g*36+tig conflict-free)

// SMEM layout (bytes)
#define OFF_W1H   0         // 18432
#define OFF_W1L   18432
#define OFF_W2H   36864     // s8 H  (18432)
#define OFF_W2L   55296
#define OFF_W3H   73728
#define OFF_W3L   92160
#define OFF_PBF   110592    // bf16 p tile (34816)
#define OFF_AU8   145408    // u8 act tile (18432)
#define OFF_B1    163840
#define OFF_B2    164352
#define OFF_B3    164864
#define OFF_S2F   165376    // per-col scale of W2 (128 f)
#define OFF_S3F   165888
#define OFF_HALF  166400    // halfmax[128][2] floats
#define OFF_SROW  167424    // per-row act scale (s/255)
#define OFF_INV   167936    // 255/s
#define OFF_ACCS  168448    // float accs[4][BB][HH] = 8192
#define SMEM_BYTES 176640

// Scratch
__device__ float g_x[BB * NN * DD];
__device__ float g_partial[GRID1 * BB * HH];

// flat triangular index p in [0, 32896) -> (i, j), j >= i
__device__ __forceinline__ int2 pair_from_flat(int p) {
    int i = (int)(256.5f - sqrtf(65792.25f - 2.0f * (float)p));
    while (i * 256 - (i * (i - 1)) / 2 > p) --i;
    while ((i + 1) * 256 - ((i + 1) * i) / 2 <= p) ++i;
    int j = i + (p - (i * 256 - (i * (i - 1)) / 2));
    return make_int2(i, j);
}

// ---------------- Kernel 0: build x ----------------
__global__ void build_x_kernel(const int* __restrict__ xcat32,
                               const float* __restrict__ xfeat,
                               const float* __restrict__ emb) {
    int row = blockIdx.x;
    int d = threadIdx.x;
    bool is64 = (xcat32[1] == 0) && (xcat32[3] == 0) && (xcat32[5] == 0) &&
                (xcat32[7] == 0) && (xcat32[9] == 0) && (xcat32[11] == 0);
    int idx = is64 ? xcat32[row * 2] : xcat32[row];
    float v = (d < EE) ? emb[idx * EE + d] : xfeat[row];
    g_x[row * DD + d] = v;
}

// ---------------- MMA wrappers ----------------
__device__ __forceinline__ void mma16816(float& c0, float& c1, float& c2, float& c3,
                                         uint32_t a0, uint32_t a1, uint32_t a2, uint32_t a3,
                                         uint32_t b0, uint32_t b1) {
    asm volatile("mma.sync.aligned.m16n8k16.row.col.f32.bf16.bf16.f32 "
                 "{%0,%1,%2,%3}, {%4,%5,%6,%7}, {%8,%9}, {%0,%1,%2,%3};"
                 : "+f"(c0), "+f"(c1), "+f"(c2), "+f"(c3)
                 : "r"(a0), "r"(a1), "r"(a2), "r"(a3), "r"(b0), "r"(b1));
}
__device__ __forceinline__ void imma16832(int& c0, int& c1, int& c2, int& c3,
                                          uint32_t a0, uint32_t a1, uint32_t a2, uint32_t a3,
                                          uint32_t b0, uint32_t b1) {
    asm volatile("mma.sync.aligned.m16n8k32.row.col.s32.u8.s8.s32 "
                 "{%0,%1,%2,%3}, {%4,%5,%6,%7}, {%8,%9}, {%0,%1,%2,%3};"
                 : "+r"(c0), "+r"(c1), "+r"(c2), "+r"(c3)
                 : "r"(a0), "r"(a1), "r"(a2), "r"(a3), "r"(b0), "r"(b1));
}
__device__ __forceinline__ uint32_t lds32(const void* p) { return *(const uint32_t*)p; }

// ---------------- bf16 layer (layer 1) ----------------
template <int KSTEPS>
__device__ __forceinline__ void run_layer_bf(const __nv_bfloat16* __restrict__ act,
                                             const __nv_bfloat16* __restrict__ Wh,
                                             const __nv_bfloat16* __restrict__ Wl,
                                             int wpitch, const float* __restrict__ bias,
                                             int m0, int f0, int g, int tig,
                                             float c[2][8][4]) {
#pragma unroll
    for (int nt = 0; nt < 8; nt++) {
        float2 bv = *(const float2*)(bias + f0 + nt * 8 + 2 * tig);
#pragma unroll
        for (int mt = 0; mt < 2; mt++) {
            c[mt][nt][0] = bv.x; c[mt][nt][1] = bv.y;
            c[mt][nt][2] = bv.x; c[mt][nt][3] = bv.y;
        }
    }
#pragma unroll 2
    for (int ks = 0; ks < KSTEPS; ks++) {
        int k = ks * 16 + 2 * tig;
        uint32_t a[2][4];
#pragma unroll
        for (int mt = 0; mt < 2; mt++) {
            const __nv_bfloat16* ar = act + (m0 + mt * 16 + g) * APITCH + k;
            a[mt][0] = lds32(ar);
            a[mt][1] = lds32(ar + 8 * APITCH);
            a[mt][2] = lds32(ar + 8);
            a[mt][3] = lds32(ar + 8 * APITCH + 8);
        }
#pragma unroll
        for (int nt = 0; nt < 8; nt++) {
            const __nv_bfloat16* wh = Wh + (f0 + nt * 8 + g) * wpitch + k;
            const __nv_bfloat16* wl = Wl + (f0 + nt * 8 + g) * wpitch + k;
            uint32_t bh0 = lds32(wh), bh1 = lds32(wh + 8);
            uint32_t bl0 = lds32(wl), bl1 = lds32(wl + 8);
#pragma unroll
            for (int mt = 0; mt < 2; mt++) {
                mma16816(c[mt][nt][0], c[mt][nt][1], c[mt][nt][2], c[mt][nt][3],
                         a[mt][0], a[mt][1], a[mt][2], a[mt][3], bh0, bh1);
                mma16816(c[mt][nt][0], c[mt][nt][1], c[mt][nt][2], c[mt][nt][3],
                         a[mt][0], a[mt][1], a[mt][2], a[mt][3], bl0, bl1);
            }
        }
    }
}

// ---------------- int8 pass: ci += au8 * Ws8 over K=128 ----------------
__device__ __forceinline__ void run_pass_int(const char* __restrict__ au8,
                                             const char* __restrict__ W,
                                             int m0, int f0, int g, int tig,
                                             int ci[2][8][4]) {
#pragma unroll
    for (int ks = 0; ks < 4; ks++) {
        int k = ks * 32 + 4 * tig;
        uint32_t a[2][4];
#pragma unroll
        for (int mt = 0; mt < 2; mt++) {
            const char* ar = au8 + (m0 + mt * 16 + g) * IPITCH + k;
            a[mt][0] = lds32(ar);
            a[mt][1] = lds32(ar + 8 * IPITCH);
            a[mt][2] = lds32(ar + 16);
            a[mt][3] = lds32(ar + 8 * IPITCH + 16);
        }
#pragma unroll
        for (int nt = 0; nt < 8; nt++) {
            const char* wr = W + (f0 + nt * 8 + g) * IPITCH + k;
            uint32_t b0 = lds32(wr), b1 = lds32(wr + 16);
#pragma unroll
            for (int mt = 0; mt < 2; mt++)
                imma16832(ci[mt][nt][0], ci[mt][nt][1], ci[mt][nt][2], ci[mt][nt][3],
                          a[mt][0], a[mt][1], a[mt][2], a[mt][3], b0, b1);
        }
    }
}

// ---------------- quantize epilogue: vv (relu'd floats) -> u8 act + row scales ----------------
// vv[mt][nt][q]: q&1 = f offset, q>>1 = +8 row offset. Updates halfmax/srow/inv in smem.
__device__ __forceinline__ void quant_store(float vv[2][8][4], char* __restrict__ au8,
                                            float* __restrict__ halfmax,
                                            float* __restrict__ srow,
                                            float* __restrict__ inv,
                                            int m0, int f0, int g, int tig,
                                            int warpcol, int tid) {
    // local row maxes
    float lm[2][2];
#pragma unroll
    for (int mt = 0; mt < 2; mt++) {
        lm[mt][0] = 0.f; lm[mt][1] = 0.f;
#pragma unroll
        for (int nt = 0; nt < 8; nt++) {
            lm[mt][0] = fmaxf(lm[mt][0], fmaxf(vv[mt][nt][0], vv[mt][nt][1]));
            lm[mt][1] = fmaxf(lm[mt][1], fmaxf(vv[mt][nt][2], vv[mt][nt][3]));
        }
    }
#pragma unroll
    for (int mt = 0; mt < 2; mt++)
#pragma unroll
        for (int h = 0; h < 2; h++) {
            float v = lm[mt][h];
            v = fmaxf(v, __shfl_xor_sync(0xffffffffu, v, 1));
            v = fmaxf(v, __shfl_xor_sync(0xffffffffu, v, 2));
            lm[mt][h] = v;
        }
    if (tig == 0) {
#pragma unroll
        for (int mt = 0; mt < 2; mt++)
#pragma unroll
            for (int h = 0; h < 2; h++)
                halfmax[(m0 + mt * 16 + g + 8 * h) * 2 + warpcol] = lm[mt][h];
    }
    __syncthreads();
    if (tid < 128) {
        float s = fmaxf(halfmax[2 * tid], halfmax[2 * tid + 1]);
        srow[tid] = s * (1.0f / 255.0f);
        inv[tid] = (s > 0.f) ? 255.0f / s : 0.f;
    }
    __syncthreads();
    // quantize + pack 2 u8 per st.u16
#pragma unroll
    for (int mt = 0; mt < 2; mt++)
#pragma unroll
        for (int h = 0; h < 2; h++) {
            int m = m0 + mt * 16 + g + 8 * h;
            float iv = inv[m];
            char* rowp = au8 + m * IPITCH + f0 + 2 * tig;
#pragma unroll
            for (int nt = 0; nt < 8; nt++) {
                uint32_t u0 = (uint32_t)__float2int_rn(vv[mt][nt][2 * h] * iv);
                uint32_t u1 = (uint32_t)__float2int_rn(vv[mt][nt][2 * h + 1] * iv);
                *(uint16_t*)(rowp + nt * 8) = (uint16_t)(u0 | (u1 << 8));
            }
        }
    __syncthreads();
}

// bf16 weight split (layer 1)
__device__ void load_w1(const float* __restrict__ W,
                        __nv_bfloat16* hi, __nv_bfloat16* lo, int tid) {
    for (int idx = tid; idx < DD * HH; idx += 256) {
        int f = idx & 127, k = idx >> 7;
        float w = W[k * HH + f];
        __nv_bfloat16 h = __float2bfloat16(w);
        hi[f * W1PITCH + k] = h;
        lo[f * W1PITCH + k] = __float2bfloat16(w - __bfloat162float(h));
    }
}

// int8 2-term weight quantization (layers 2/3): per-column 14-bit
__device__ void load_w_int(const float* __restrict__ W, char* H, char* L,
                           float* sf, int tid) {
    if (tid < 128) {
        int f = tid;
        float mx = 0.f;
        for (int k = 0; k < HH; k++) mx = fmaxf(mx, fabsf(W[k * HH + f]));
        float s = (mx > 0.f) ? mx / 16256.0f : 1.0f;
        float iv = (mx > 0.f) ? 16256.0f / mx : 0.f;
        sf[f] = s;
        for (int k = 0; k < HH; k++) {
            int iw = __float2int_rn(W[k * HH + f] * iv);
            int h = (iw + 64) >> 7;
            int l = iw - (h << 7);
            H[f * IPITCH + k] = (char)h;
            L[f * IPITCH + k] = (char)l;
        }
    }
}

// ---------------- Kernel 1: persistent pair-MLP (bf16 L1 + int8 L2/L3) ----------------
__global__ void __launch_bounds__(256, 1)
pair_mlp_kernel(const float* __restrict__ W1, const float* __restrict__ b1,
                const float* __restrict__ W2, const float* __restrict__ b2,
                const float* __restrict__ W3, const float* __restrict__ b3) {
    extern __shared__ char sm[];
    __nv_bfloat16* W1h = (__nv_bfloat16*)(sm + OFF_W1H);
    __nv_bfloat16* W1l = (__nv_bfloat16*)(sm + OFF_W1L);
    char* W2H = sm + OFF_W2H; char* W2L = sm + OFF_W2L;
    char* W3H = sm + OFF_W3H; char* W3L = sm + OFF_W3L;
    __nv_bfloat16* pbf = (__nv_bfloat16*)(sm + OFF_PBF);
    char* au8 = sm + OFF_AU8;
    float* b1s = (float*)(sm + OFF_B1);
    float* b2s = (float*)(sm + OFF_B2);
    float* b3s = (float*)(sm + OFF_B3);
    float* s2f = (float*)(sm + OFF_S2F);
    float* s3f = (float*)(sm + OFF_S3F);
    float* halfmax = (float*)(sm + OFF_HALF);
    float* srow = (float*)(sm + OFF_SROW);
    float* inv  = (float*)(sm + OFF_INV);
    float* accs = (float*)(sm + OFF_ACCS);

    const int tid = threadIdx.x;
    const int warp = tid >> 5, lane = tid & 31;
    const int g = lane >> 2, tig = lane & 3;
    const int m0 = (warp >> 1) * 32;
    const int f0 = (warp & 1) * 64;
    const int strip = warp >> 1, warpcol = warp & 1;

    load_w1(W1, W1h, W1l, tid);
    load_w_int(W2, W2H, W2L, s2f, tid);
    load_w_int(W3, W3H, W3L, s3f, tid);
    if (tid < 128) { b1s[tid] = b1[tid]; b2s[tid] = b2[tid]; b3s[tid] = b3[tid]; }
    for (int idx = tid; idx < 4 * BB * HH; idx += 256) accs[idx] = 0.f;
    __syncthreads();

    float c[2][8][4];
    float vv[2][8][4];
    int ci[2][8][4];

    for (int t = blockIdx.x; t < NTILES; t += GRID1) {
        int b = t / TILES_PER_B;
        int r = t - b * TILES_PER_B;
        int P0 = r * 128;

        // ---- build p tile (bf16) ----
        {
            int m = tid >> 1;
            int kh = (tid & 1) * 32;
            int2 ij = pair_from_flat(P0 + m);
            const float4* xi = (const float4*)(g_x + (b * NN + ij.x) * DD + kh);
            const float4* xj = (const float4*)(g_x + (b * NN + ij.y) * DD + kh);
            __nv_bfloat16* row = pbf + m * APITCH + kh;
#pragma unroll
            for (int q = 0; q < 8; q++) {
                float4 a4 = xi[q], c4 = xj[q];
                __nv_bfloat162 v, w;
                v.x = __float2bfloat16(a4.x * c4.x);
                v.y = __float2bfloat16(a4.y * c4.y);
                w.x = __float2bfloat16(a4.z * c4.z);
                w.y = __float2bfloat16(a4.w * c4.w);
                *(__nv_bfloat162*)(row + q * 4)     = v;
                *(__nv_bfloat162*)(row + q * 4 + 2) = w;
            }
        }
        __syncthreads();

        // ---- Layer 1: bf16 2-term, K=64 ----
        run_layer_bf<4>(pbf, W1h, W1l, W1PITCH, b1s, m0, f0, g, tig, c);
        __syncthreads();
#pragma unroll
        for (int mt = 0; mt < 2; mt++)
#pragma unroll
            for (int nt = 0; nt < 8; nt++)
#pragma unroll
                for (int q = 0; q < 4; q++)
                    vv[mt][nt][q] = fmaxf(c[mt][nt][q], 0.f);
        quant_store(vv, au8, halfmax, srow, inv, m0, f0, g, tig, warpcol, tid);

        // ---- Layer 2: int8 (u8 act, 14-bit weights via 2 passes) ----
#pragma unroll
        for (int mt = 0; mt < 2; mt++)
#pragma unroll
            for (int nt = 0; nt < 8; nt++)
#pragma unroll
                for (int q = 0; q < 4; q++) ci[mt][nt][q] = 0;
        run_pass_int(au8, W2H, m0, f0, g, tig, ci);
#pragma unroll
        for (int mt = 0; mt < 2; mt++)
#pragma unroll
            for (int nt = 0; nt < 8; nt++)
#pragma unroll
                for (int q = 0; q < 4; q++) ci[mt][nt][q] <<= 7;
        run_pass_int(au8, W2L, m0, f0, g, tig, ci);
        __syncthreads();
        // dequant + bias + relu (reads srow BEFORE quant_store overwrites it)
#pragma unroll
        for (int nt = 0; nt < 8; nt++) {
            int f = f0 + nt * 8 + 2 * tig;
            float2 sv = *(const float2*)(s2f + f);
            float2 bv = *(const float2*)(b2s + f);
#pragma unroll
            for (int mt = 0; mt < 2; mt++) {
                float sr0 = srow[m0 + mt * 16 + g];
                float sr1 = srow[m0 + mt * 16 + g + 8];
                vv[mt][nt][0] = fmaxf(fmaf((float)ci[mt][nt][0], sr0 * sv.x, bv.x), 0.f);
                vv[mt][nt][1] = fmaxf(fmaf((float)ci[mt][nt][1], sr0 * sv.y, bv.y), 0.f);
                vv[mt][nt][2] = fmaxf(fmaf((float)ci[mt][nt][2], sr1 * sv.x, bv.x), 0.f);
                vv[mt][nt][3] = fmaxf(fmaf((float)ci[mt][nt][3], sr1 * sv.y, bv.y), 0.f);
            }
        }
        quant_store(vv, au8, halfmax, srow, inv, m0, f0, g, tig, warpcol, tid);

        // ---- Layer 3: int8 -> reduce ----
#pragma unroll
        for (int mt = 0; mt < 2; mt++)
#pragma unroll
            for (int nt = 0; nt < 8; nt++)
#pragma unroll
                for (int q = 0; q < 4; q++) ci[mt][nt][q] = 0;
        run_pass_int(au8, W3H, m0, f0, g, tig, ci);
#pragma unroll
        for (int mt = 0; mt < 2; mt++)
#pragma unroll
            for (int nt = 0; nt < 8; nt++)
#pragma unroll
                for (int q = 0; q < 4; q++) ci[mt][nt][q] <<= 7;
        run_pass_int(au8, W3L, m0, f0, g, tig, ci);

        // pair multiplicity weights
        float wm[2][2];
#pragma unroll
        for (int mt = 0; mt < 2; mt++)
#pragma unroll
            for (int h = 0; h < 2; h++) {
                int2 ij = pair_from_flat(P0 + m0 + mt * 16 + g + h * 8);
                wm[mt][h] = (ij.x == ij.y) ? 1.f : 2.f;
            }
#pragma unroll
        for (int nt = 0; nt < 8; nt++) {
            int f = f0 + nt * 8 + 2 * tig;
            float2 sv = *(const float2*)(s3f + f);
            float2 bv = *(const float2*)(b3s + f);
            float s0 = 0.f, s1 = 0.f;
#pragma unroll
            for (int mt = 0; mt < 2; mt++) {
                float sr0 = srow[m0 + mt * 16 + g];
                float sr1 = srow[m0 + mt * 16 + g + 8];
                s0 += wm[mt][0] * fmaxf(fmaf((float)ci[mt][nt][0], sr0 * sv.x, bv.x), 0.f)
                    + wm[mt][1] * fmaxf(fmaf((float)ci[mt][nt][2], sr1 * sv.x, bv.x), 0.f);
                s1 += wm[mt][0] * fmaxf(fmaf((float)ci[mt][nt][1], sr0 * sv.y, bv.y), 0.f)
                    + wm[mt][1] * fmaxf(fmaf((float)ci[mt][nt][3], sr1 * sv.y, bv.y), 0.f);
            }
            s0 += __shfl_xor_sync(0xffffffffu, s0, 4);
            s0 += __shfl_xor_sync(0xffffffffu, s0, 8);
            s0 += __shfl_xor_sync(0xffffffffu, s0, 16);
            s1 += __shfl_xor_sync(0xffffffffu, s1, 4);
            s1 += __shfl_xor_sync(0xffffffffu, s1, 8);
            s1 += __shfl_xor_sync(0xffffffffu, s1, 16);
            if (lane < 4) {
                float* ap = accs + (strip * BB + b) * HH + f0 + nt * 8 + 2 * tig;
                ap[0] += s0;
                ap[1] += s1;
            }
        }
        __syncthreads();
    }

    for (int idx = tid; idx < BB * HH; idx += 256) {
        float s = accs[idx] + accs[BB * HH + idx] +
                  accs[2 * BB * HH + idx] + accs[3 * BB * HH + idx];
        g_partial[blockIdx.x * (BB * HH) + idx] = s;
    }
}

// ---------------- Kernel 2: reduce + mean + relu + decoder MLP ----------------
__global__ void finalize_kernel(const float* __restrict__ D1, const float* __restrict__ c1,
                                const float* __restrict__ D2, const float* __restrict__ c2,
                                const float* __restrict__ D3, const float* __restrict__ c3,
                                float* __restrict__ out) {
    __shared__ float ha[BB * HH];
    __shared__ float hb[BB * HH];
    int tid = threadIdx.x;
    float s = 0.f;
    for (int cta = 0; cta < GRID1; cta++)
        s += g_partial[cta * (BB * HH) + tid];
    s *= (1.0f / (float)(NN * NN));
    ha[tid] = fmaxf(s, 0.f);
    __syncthreads();

    int b = tid >> 7, f = tid & 127;
    float v = c1[f];
    for (int k = 0; k < HH; k++) v += ha[b * HH + k] * D1[k * HH + f];
    hb[tid] = fmaxf(v, 0.f);
    __syncthreads();

    v = c2[f];
    for (int k = 0; k < HH; k++) v += hb[b * HH + k] * D2[k * HH + f];
    ha[tid] = fmaxf(v, 0.f);
    __syncthreads();

    if (tid < BB) {
        float o = c3[0];
        for (int k = 0; k < HH; k++) o += ha[tid * HH + k] * D3[k];
        out[tid] = o;
    }
}

// ---------------- Launch ----------------
extern "C" void kernel_launch(void* const* d_in, const int* in_sizes, int n_in,
                              void* d_out, int out_size) {
    const int*   xcat  = (const int*)d_in[0];
    const float* xfeat = (const float*)d_in[1];
    const float* emb   = (const float*)d_in[2];
    const float* W1 = (const float*)d_in[3];
    const float* b1 = (const float*)d_in[4];
    const float* W2 = (const float*)d_in[5];
    const float* b2 = (const float*)d_in[6];
    const float* W3 = (const float*)d_in[7];
    const float* b3 = (const float*)d_in[8];
    const float* D1 = (const float*)d_in[9];
    const float* c1 = (const float*)d_in[10];
    const float* D2 = (const float*)d_in[11];
    const float* c2 = (const float*)d_in[12];
    const float* D3 = (const float*)d_in[13];
    const float* c3 = (const float*)d_in[14];
    float* out = (float*)d_out;

    cudaFuncSetAttribute(pair_mlp_kernel,
                         cudaFuncAttributeMaxDynamicSharedMemorySize, SMEM_BYTES);

    build_x_kernel<<<BB * NN, DD>>>(xcat, xfeat, emb);
    pair_mlp_kernel<<<GRID1, 256, SMEM_BYTES>>>(W1, b1, W2, b2, W3, b3);
    finalize_kernel<<<1, 512>>>(D1, c1, D2, c2, D3, c3, out);
}

// round 6
// speedup vs baseline: 2.4322x; 2.4322x over previous
#include <cuda_runtime.h>
#include <cuda_fp16.h>
#include <cstdint>

// Problem constants
#define BB 4
#define NN 256
#define EE 63
#define DD 64
#define HH 128

// Exact triangular packing: per b, 256*257/2 = 32896 pairs = 257 tiles of 128.
#define TILES_PER_B 257
#define NTILES (BB * TILES_PER_B)
#define GRID1 152

#define APITCH 136      // fp16 elems per row (68 words: conflict-free)
#define W1PITCH 72

// SMEM layout (bytes)
#define OFF_W1H 0            // 18432
#define OFF_W1L 18432        // 18432
#define OFF_W2  36864        // 34816 (single fp16, pitch APITCH)
#define OFF_W3  71680        // 34816
#define OFF_ACT 106496       // 34816
#define OFF_B1  141312
#define OFF_B2  141824
#define OFF_B3  142336
#define OFF_ACCS 142848      // float accs[4][BB][HH] = 8192
#define SMEM_BYTES 151040

// Scratch
__device__ float g_x[BB * NN * DD];
__device__ float g_partial[GRID1 * BB * HH];

// flat triangular index p in [0, 32896) -> (i, j), j >= i
__device__ __forceinline__ int2 pair_from_flat(int p) {
    int i = (int)(256.5f - sqrtf(65792.25f - 2.0f * (float)p));
    while (i * 256 - (i * (i - 1)) / 2 > p) --i;
    while ((i + 1) * 256 - ((i + 1) * i) / 2 <= p) ++i;
    int j = i + (p - (i * 256 - (i * (i - 1)) / 2));
    return make_int2(i, j);
}

// ---------------- Kernel 0: build x = concat(emb[xcat], xfeat) ----------------
__global__ void build_x_kernel(const int* __restrict__ xcat32,
                               const float* __restrict__ xfeat,
                               const float* __restrict__ emb) {
    int row = blockIdx.x;
    int d = threadIdx.x;
    bool is64 = (xcat32[1] == 0) && (xcat32[3] == 0) && (xcat32[5] == 0) &&
                (xcat32[7] == 0) && (xcat32[9] == 0) && (xcat32[11] == 0);
    int idx = is64 ? xcat32[row * 2] : xcat32[row];
    float v = (d < EE) ? emb[idx * EE + d] : xfeat[row];
    g_x[row * DD + d] = v;
}

// ---------------- HMMA m16n8k16 fp16 (f32 accum) ----------------
__device__ __forceinline__ void mma16816(float& c0, float& c1, float& c2, float& c3,
                                         uint32_t a0, uint32_t a1, uint32_t a2, uint32_t a3,
                                         uint32_t b0, uint32_t b1) {
    asm volatile("mma.sync.aligned.m16n8k16.row.col.f32.f16.f16.f32 "
                 "{%0,%1,%2,%3}, {%4,%5,%6,%7}, {%8,%9}, {%0,%1,%2,%3};"
                 : "+f"(c0), "+f"(c1), "+f"(c2), "+f"(c3)
                 : "r"(a0), "r"(a1), "r"(a2), "r"(a3), "r"(b0), "r"(b1));
}

__device__ __forceinline__ uint32_t lds32(const void* p) { return *(const uint32_t*)p; }

// One GEMM layer. TWO=true adds the Wl low-order term (2-term split).
template <int KSTEPS, bool TWO>
__device__ __forceinline__ void run_layer(const __half* __restrict__ act,
                                          const __half* __restrict__ Wh,
                                          const __half* __restrict__ Wl,
                                          int wpitch, const float* __restrict__ bias,
                                          int m0, int f0, int g, int tig,
                                          float c[2][8][4]) {
#pragma unroll
    for (int nt = 0; nt < 8; nt++) {
        float2 bv = *(const float2*)(bias + f0 + nt * 8 + 2 * tig);
#pragma unroll
        for (int mt = 0; mt < 2; mt++) {
            c[mt][nt][0] = bv.x; c[mt][nt][1] = bv.y;
            c[mt][nt][2] = bv.x; c[mt][nt][3] = bv.y;
        }
    }
#pragma unroll 2
    for (int ks = 0; ks < KSTEPS; ks++) {
        int k = ks * 16 + 2 * tig;
        uint32_t a[2][4];
#pragma unroll
        for (int mt = 0; mt < 2; mt++) {
            const __half* ar = act + (m0 + mt * 16 + g) * APITCH + k;
            a[mt][0] = lds32(ar);
            a[mt][1] = lds32(ar + 8 * APITCH);
            a[mt][2] = lds32(ar + 8);
            a[mt][3] = lds32(ar + 8 * APITCH + 8);
        }
#pragma unroll
        for (int nt = 0; nt < 8; nt++) {
            const __half* wh = Wh + (f0 + nt * 8 + g) * wpitch + k;
            uint32_t bh0 = lds32(wh), bh1 = lds32(wh + 8);
#pragma unroll
            for (int mt = 0; mt < 2; mt++)
                mma16816(c[mt][nt][0], c[mt][nt][1], c[mt][nt][2], c[mt][nt][3],
                         a[mt][0], a[mt][1], a[mt][2], a[mt][3], bh0, bh1);
            if (TWO) {
                const __half* wl = Wl + (f0 + nt * 8 + g) * wpitch + k;
                uint32_t bl0 = lds32(wl), bl1 = lds32(wl + 8);
#pragma unroll
                for (int mt = 0; mt < 2; mt++)
                    mma16816(c[mt][nt][0], c[mt][nt][1], c[mt][nt][2], c[mt][nt][3],
                             a[mt][0], a[mt][1], a[mt][2], a[mt][3], bl0, bl1);
            }
        }
    }
}

// relu + store as next activation (fp16), conflict-free STS.32
__device__ __forceinline__ void store_act(__half* __restrict__ act,
                                          int m0, int f0, int g, int tig,
                                          float c[2][8][4]) {
#pragma unroll
    for (int mt = 0; mt < 2; mt++) {
        int m = m0 + mt * 16 + g;
#pragma unroll
        for (int nt = 0; nt < 8; nt++) {
            int f = f0 + nt * 8 + 2 * tig;
            __half2 v = __floats2half2_rn(fmaxf(c[mt][nt][0], 0.f),
                                          fmaxf(c[mt][nt][1], 0.f));
            *(__half2*)(act + m * APITCH + f) = v;
            __half2 w = __floats2half2_rn(fmaxf(c[mt][nt][2], 0.f),
                                          fmaxf(c[mt][nt][3], 0.f));
            *(__half2*)(act + (m + 8) * APITCH + f) = w;
        }
    }
}

// W1: transpose + 2-term fp16 split
__device__ void load_w1(const float* __restrict__ W,
                        __half* hi, __half* lo, int tid) {
    for (int idx = tid; idx < DD * HH; idx += 256) {
        int f = idx & 127, k = idx >> 7;
        float w = W[k * HH + f];
        __half h = __float2half(w);
        hi[f * W1PITCH + k] = h;
        lo[f * W1PITCH + k] = __float2half(w - __half2float(h));
    }
}

// W2/W3: transpose, single fp16
__device__ void load_w(const float* __restrict__ W, __half* dst, int tid) {
    for (int idx = tid; idx < HH * HH; idx += 256) {
        int f = idx & 127, k = idx >> 7;
        dst[f * APITCH + k] = __float2half(W[k * HH + f]);
    }
}

// ---------------- Kernel 1: persistent HMMA fp16 pair-MLP ----------------
__global__ void __launch_bounds__(256, 1)
pair_mlp_kernel(const float* __restrict__ W1, const float* __restrict__ b1,
                const float* __restrict__ W2, const float* __restrict__ b2,
                const float* __restrict__ W3, const float* __restrict__ b3) {
    extern __shared__ char sm[];
    __half* W1h = (__half*)(sm + OFF_W1H);
    __half* W1l = (__half*)(sm + OFF_W1L);
    __half* W2s = (__half*)(sm + OFF_W2);
    __half* W3s = (__half*)(sm + OFF_W3);
    __half* act = (__half*)(sm + OFF_ACT);
    float* b1s = (float*)(sm + OFF_B1);
    float* b2s = (float*)(sm + OFF_B2);
    float* b3s = (float*)(sm + OFF_B3);
    float* accs = (float*)(sm + OFF_ACCS);

    const int tid = threadIdx.x;
    const int warp = tid >> 5, lane = tid & 31;
    const int g = lane >> 2, tig = lane & 3;
    const int m0 = (warp >> 1) * 32;
    const int f0 = (warp & 1) * 64;
    const int strip = warp >> 1;

    load_w1(W1, W1h, W1l, tid);
    load_w(W2, W2s, tid);
    load_w(W3, W3s, tid);
    if (tid < 128) { b1s[tid] = b1[tid]; b2s[tid] = b2[tid]; b3s[tid] = b3[tid]; }
    for (int idx = tid; idx < 4 * BB * HH; idx += 256) accs[idx] = 0.f;
    __syncthreads();

    float c[2][8][4];

    for (int t = blockIdx.x; t < NTILES; t += GRID1) {
        int b = t / TILES_PER_B;
        int r = t - b * TILES_PER_B;
        int P0 = r * 128;

        // ---- build p tile: act[m][k] = fp16(x[b,im,k] * x[b,jm,k]) ----
        {
            int m = tid >> 1;
            int kh = (tid & 1) * 32;
            int2 ij = pair_from_flat(P0 + m);
            const float4* xi = (const float4*)(g_x + (b * NN + ij.x) * DD + kh);
            const float4* xj = (const float4*)(g_x + (b * NN + ij.y) * DD + kh);
            __half* row = act + m * APITCH + kh;
#pragma unroll
            for (int q = 0; q < 8; q++) {
                float4 a4 = xi[q], c4 = xj[q];
                *(__half2*)(row + q * 4)     = __floats2half2_rn(a4.x * c4.x, a4.y * c4.y);
                *(__half2*)(row + q * 4 + 2) = __floats2half2_rn(a4.z * c4.z, a4.w * c4.w);
            }
        }
        __syncthreads();

        // Layer 1 (K=64, 2-term fp16)
        run_layer<4, true>(act, W1h, W1l, W1PITCH, b1s, m0, f0, g, tig, c);
        __syncthreads();
        store_act(act, m0, f0, g, tig, c);
        __syncthreads();

        // Layer 2 (K=128, single fp16)
        run_layer<8, false>(act, W2s, (const __half*)nullptr, APITCH, b2s, m0, f0, g, tig, c);
        __syncthreads();
        store_act(act, m0, f0, g, tig, c);
        __syncthreads();

        // Layer 3 (K=128, single fp16) -> relu + multiplicity + pooled reduce
        run_layer<8, false>(act, W3s, (const __half*)nullptr, APITCH, b3s, m0, f0, g, tig, c);

        float wm[2][2];
#pragma unroll
        for (int mt = 0; mt < 2; mt++)
#pragma unroll
            for (int h = 0; h < 2; h++) {
                int2 ij = pair_from_flat(P0 + m0 + mt * 16 + g + h * 8);
                wm[mt][h] = (ij.x == ij.y) ? 1.f : 2.f;
            }
#pragma unroll
        for (int nt = 0; nt < 8; nt++) {
            float s0 = 0.f, s1 = 0.f;
#pragma unroll
            for (int mt = 0; mt < 2; mt++) {
                s0 += wm[mt][0] * fmaxf(c[mt][nt][0], 0.f) + wm[mt][1] * fmaxf(c[mt][nt][2], 0.f);
                s1 += wm[mt][0] * fmaxf(c[mt][nt][1], 0.f) + wm[mt][1] * fmaxf(c[mt][nt][3], 0.f);
            }
            s0 += __shfl_xor_sync(0xffffffffu, s0, 4);
            s0 += __shfl_xor_sync(0xffffffffu, s0, 8);
            s0 += __shfl_xor_sync(0xffffffffu, s0, 16);
            s1 += __shfl_xor_sync(0xffffffffu, s1, 4);
            s1 += __shfl_xor_sync(0xffffffffu, s1, 8);
            s1 += __shfl_xor_sync(0xffffffffu, s1, 16);
            if (lane < 4) {
                float* ap = accs + (strip * BB + b) * HH + f0 + nt * 8 + 2 * tig;
                ap[0] += s0;
                ap[1] += s1;
            }
        }
        __syncthreads();
    }

    for (int idx = tid; idx < BB * HH; idx += 256) {
        float s = accs[idx] + accs[BB * HH + idx] +
                  accs[2 * BB * HH + idx] + accs[3 * BB * HH + idx];
        g_partial[blockIdx.x * (BB * HH) + idx] = s;
    }
}

// ---------------- Kernel 2: reduce + mean + relu + decoder MLP ----------------
__global__ void finalize_kernel(const float* __restrict__ D1, const float* __restrict__ c1,
                                const float* __restrict__ D2, const float* __restrict__ c2,
                                const float* __restrict__ D3, const float* __restrict__ c3,
                                float* __restrict__ out) {
    __shared__ float ha[BB * HH];
    __shared__ float hb[BB * HH];
    int tid = threadIdx.x;
    float s = 0.f;
    for (int cta = 0; cta < GRID1; cta++)
        s += g_partial[cta * (BB * HH) + tid];
    s *= (1.0f / (float)(NN * NN));
    ha[tid] = fmaxf(s, 0.f);
    __syncthreads();

    int b = tid >> 7, f = tid & 127;
    float v = c1[f];
    for (int k = 0; k < HH; k++) v += ha[b * HH + k] * D1[k * HH + f];
    hb[tid] = fmaxf(v, 0.f);
    __syncthreads();

    v = c2[f];
    for (int k = 0; k < HH; k++) v += hb[b * HH + k] * D2[k * HH + f];
    ha[tid] = fmaxf(v, 0.f);
    __syncthreads();

    if (tid < BB) {
        float o = c3[0];
        for (int k = 0; k < HH; k++) o += ha[tid * HH + k] * D3[k];
        out[tid] = o;
    }
}

// ---------------- Launch ----------------
extern "C" void kernel_launch(void* const* d_in, const int* in_sizes, int n_in,
                              void* d_out, int out_size) {
    const int*   xcat  = (const int*)d_in[0];
    const float* xfeat = (const float*)d_in[1];
    const float* emb   = (const float*)d_in[2];
    const float* W1 = (const float*)d_in[3];
    const float* b1 = (const float*)d_in[4];
    const float* W2 = (const float*)d_in[5];
    const float* b2 = (const float*)d_in[6];
    const float* W3 = (const float*)d_in[7];
    const float* b3 = (const float*)d_in[8];
    const float* D1 = (const float*)d_in[9];
    const float* c1 = (const float*)d_in[10];
    const float* D2 = (const float*)d_in[11];
    const float* c2 = (const float*)d_in[12];
    const float* D3 = (const float*)d_in[13];
    const float* c3 = (const float*)d_in[14];
    float* out = (float*)d_out;

    cudaFuncSetAttribute(pair_mlp_kernel,
                         cudaFuncAttributeMaxDynamicSharedMemorySize, SMEM_BYTES);

    build_x_kernel<<<BB * NN, DD>>>(xcat, xfeat, emb);
    pair_mlp_kernel<<<GRID1, 256, SMEM_BYTES>>>(W1, b1, W2, b2, W3, b3);
    finalize_kernel<<<1, 512>>>(D1, c1, D2, c2, D3, c3, out);
}

// round 7
// speedup vs baseline: 2.5664x; 1.0552x over previous
#include <cuda_runtime.h>
#include <cuda_fp16.h>
#include <cstdint>

// Problem constants
#define BB 4
#define NN 256
#define EE 63
#define DD 64
#define HH 128

// 64-pair tiles, exact triangular packing: 32896/64 = 514 tiles per b.
#define TILES2_PER_B 514
#define NTILES2 (BB * TILES2_PER_B)
#define GRID1 152
#define NGROUPS (GRID1 * 2)

#define APITCH 136      // fp16 elems per row (68 words: conflict-free)
#define W1PITCH 72

// SMEM layout (bytes)
#define OFF_W1   0           // 18432
#define OFF_W2   18432       // 34816
#define OFF_W3   53248       // 34816
#define OFF_ACT0 88064       // 64*136*2 = 17408
#define OFF_ACT1 105472      // 17408
#define OFF_B1   122880
#define OFF_B2   123392
#define OFF_B3   123904
#define OFF_ACCS 124416      // float accs[4][BB][HH] = 8192
#define SMEM_BYTES 132608

// Scratch
__device__ float g_x[BB * NN * DD];
__device__ float g_partial[GRID1 * BB * HH];

// flat triangular index p in [0, 32896) -> (i, j), j >= i
__device__ __forceinline__ int2 pair_from_flat(int p) {
    int i = (int)(256.5f - sqrtf(65792.25f - 2.0f * (float)p));
    while (i * 256 - (i * (i - 1)) / 2 > p) --i;
    while ((i + 1) * 256 - ((i + 1) * i) / 2 <= p) ++i;
    int j = i + (p - (i * 256 - (i * (i - 1)) / 2));
    return make_int2(i, j);
}

#define GBAR(id) asm volatile("bar.sync %0, %1;" :: "r"(id), "r"(128) : "memory")

// ---------------- Kernel 0: build x = concat(emb[xcat], xfeat) ----------------
__global__ void build_x_kernel(const int* __restrict__ xcat32,
                               const float* __restrict__ xfeat,
                               const float* __restrict__ emb) {
    int row = blockIdx.x;
    int d = threadIdx.x;
    bool is64 = (xcat32[1] == 0) && (xcat32[3] == 0) && (xcat32[5] == 0) &&
                (xcat32[7] == 0) && (xcat32[9] == 0) && (xcat32[11] == 0);
    int idx = is64 ? xcat32[row * 2] : xcat32[row];
    float v = (d < EE) ? emb[idx * EE + d] : xfeat[row];
    g_x[row * DD + d] = v;
}

// ---------------- HMMA m16n8k16 fp16 (f32 accum) ----------------
__device__ __forceinline__ void mma16816(float& c0, float& c1, float& c2, float& c3,
                                         uint32_t a0, uint32_t a1, uint32_t a2, uint32_t a3,
                                         uint32_t b0, uint32_t b1) {
    asm volatile("mma.sync.aligned.m16n8k16.row.col.f32.f16.f16.f32 "
                 "{%0,%1,%2,%3}, {%4,%5,%6,%7}, {%8,%9}, {%0,%1,%2,%3};"
                 : "+f"(c0), "+f"(c1), "+f"(c2), "+f"(c3)
                 : "r"(a0), "r"(a1), "r"(a2), "r"(a3), "r"(b0), "r"(b1));
}

__device__ __forceinline__ uint32_t lds32(const void* p) { return *(const uint32_t*)p; }

// One GEMM layer over a 64-row act tile; warp computes m0..m0+31 x f0..f0+63.
template <int KSTEPS>
__device__ __forceinline__ void run_layer(const __half* __restrict__ act,
                                          const __half* __restrict__ W,
                                          int wpitch, const float* __restrict__ bias,
                                          int m0, int f0, int g, int tig,
                                          float c[2][8][4]) {
#pragma unroll
    for (int nt = 0; nt < 8; nt++) {
        float2 bv = *(const float2*)(bias + f0 + nt * 8 + 2 * tig);
#pragma unroll
        for (int mt = 0; mt < 2; mt++) {
            c[mt][nt][0] = bv.x; c[mt][nt][1] = bv.y;
            c[mt][nt][2] = bv.x; c[mt][nt][3] = bv.y;
        }
    }
#pragma unroll 2
    for (int ks = 0; ks < KSTEPS; ks++) {
        int k = ks * 16 + 2 * tig;
        uint32_t a[2][4];
#pragma unroll
        for (int mt = 0; mt < 2; mt++) {
            const __half* ar = act + (m0 + mt * 16 + g) * APITCH + k;
            a[mt][0] = lds32(ar);
            a[mt][1] = lds32(ar + 8 * APITCH);
            a[mt][2] = lds32(ar + 8);
            a[mt][3] = lds32(ar + 8 * APITCH + 8);
        }
#pragma unroll
        for (int nt = 0; nt < 8; nt++) {
            const __half* wr = W + (f0 + nt * 8 + g) * wpitch + k;
            uint32_t b0 = lds32(wr), b1 = lds32(wr + 8);
#pragma unroll
            for (int mt = 0; mt < 2; mt++)
                mma16816(c[mt][nt][0], c[mt][nt][1], c[mt][nt][2], c[mt][nt][3],
                         a[mt][0], a[mt][1], a[mt][2], a[mt][3], b0, b1);
        }
    }
}

__device__ __forceinline__ void store_act(__half* __restrict__ act,
                                          int m0, int f0, int g, int tig,
                                          float c[2][8][4]) {
#pragma unroll
    for (int mt = 0; mt < 2; mt++) {
        int m = m0 + mt * 16 + g;
#pragma unroll
        for (int nt = 0; nt < 8; nt++) {
            int f = f0 + nt * 8 + 2 * tig;
            *(__half2*)(act + m * APITCH + f) =
                __floats2half2_rn(fmaxf(c[mt][nt][0], 0.f), fmaxf(c[mt][nt][1], 0.f));
            *(__half2*)(act + (m + 8) * APITCH + f) =
                __floats2half2_rn(fmaxf(c[mt][nt][2], 0.f), fmaxf(c[mt][nt][3], 0.f));
        }
    }
}

// transpose weights into SMEM (single fp16)
__device__ void load_w(const float* __restrict__ W, int K, __half* dst, int pitch, int tid) {
    for (int idx = tid; idx < K * HH; idx += 256) {
        int f = idx & 127, k = idx >> 7;
        dst[f * pitch + k] = __float2half(W[k * HH + f]);
    }
}

// ---------------- Kernel 1: persistent fp16 pair-MLP, 2 groups/CTA ----------------
__global__ void __launch_bounds__(256, 1)
pair_mlp_kernel(const float* __restrict__ W1, const float* __restrict__ b1,
                const float* __restrict__ W2, const float* __restrict__ b2,
                const float* __restrict__ W3, const float* __restrict__ b3) {
    extern __shared__ char sm[];
    __half* W1s = (__half*)(sm + OFF_W1);
    __half* W2s = (__half*)(sm + OFF_W2);
    __half* W3s = (__half*)(sm + OFF_W3);
    float* b1s = (float*)(sm + OFF_B1);
    float* b2s = (float*)(sm + OFF_B2);
    float* b3s = (float*)(sm + OFF_B3);
    float* accs = (float*)(sm + OFF_ACCS);

    const int tid = threadIdx.x;
    const int warp = tid >> 5, lane = tid & 31;
    const int g = lane >> 2, tig = lane & 3;
    const int grp = warp >> 2;                  // group 0 or 1
    const int wg = warp & 3;                    // warp within group
    const int m0 = (wg >> 1) * 32;
    const int f0 = (wg & 1) * 64;
    const int strip = grp * 2 + (wg >> 1);      // 0..3, disjoint accs region
    const int bar = grp + 1;                    // named barrier id
    __half* act = (__half*)(sm + (grp ? OFF_ACT1 : OFF_ACT0));

    load_w(W1, DD, W1s, W1PITCH, tid);
    load_w(W2, HH, W2s, APITCH, tid);
    load_w(W3, HH, W3s, APITCH, tid);
    if (tid < 128) { b1s[tid] = b1[tid]; b2s[tid] = b2[tid]; b3s[tid] = b3[tid]; }
    for (int idx = tid; idx < 4 * BB * HH; idx += 256) accs[idx] = 0.f;
    __syncthreads();

    float c[2][8][4];
    const int tg = tid & 127;                   // thread id within group

    for (int t = blockIdx.x * 2 + grp; t < NTILES2; t += NGROUPS) {
        int b = t / TILES2_PER_B;
        int r = t - b * TILES2_PER_B;
        int P0 = r * 64;                        // flat pair base (64 pairs/tile)

        // ---- build p tile: act[m][k] = fp16(x[b,im,k] * x[b,jm,k]), m<64 ----
        {
            int m = tg >> 1;
            int kh = (tg & 1) * 32;
            int2 ij = pair_from_flat(P0 + m);
            const float4* xi = (const float4*)(g_x + (b * NN + ij.x) * DD + kh);
            const float4* xj = (const float4*)(g_x + (b * NN + ij.y) * DD + kh);
            __half* row = act + m * APITCH + kh;
#pragma unroll
            for (int q = 0; q < 8; q++) {
                float4 a4 = xi[q], c4 = xj[q];
                *(__half2*)(row + q * 4)     = __floats2half2_rn(a4.x * c4.x, a4.y * c4.y);
                *(__half2*)(row + q * 4 + 2) = __floats2half2_rn(a4.z * c4.z, a4.w * c4.w);
            }
        }
        GBAR(bar);

        // Layer 1 (K=64)
        run_layer<4>(act, W1s, W1PITCH, b1s, m0, f0, g, tig, c);
        GBAR(bar);
        store_act(act, m0, f0, g, tig, c);
        GBAR(bar);

        // Layer 2 (K=128)
        run_layer<8>(act, W2s, APITCH, b2s, m0, f0, g, tig, c);
        GBAR(bar);
        store_act(act, m0, f0, g, tig, c);
        GBAR(bar);

        // Layer 3 (K=128) -> relu + multiplicity + pooled reduce
        run_layer<8>(act, W3s, APITCH, b3s, m0, f0, g, tig, c);

        float wm[2][2];
#pragma unroll
        for (int mt = 0; mt < 2; mt++)
#pragma unroll
            for (int h = 0; h < 2; h++) {
                int2 ij = pair_from_flat(P0 + m0 + mt * 16 + g + h * 8);
                wm[mt][h] = (ij.x == ij.y) ? 1.f : 2.f;
            }
#pragma unroll
        for (int nt = 0; nt < 8; nt++) {
            float s0 = 0.f, s1 = 0.f;
#pragma unroll
            for (int mt = 0; mt < 2; mt++) {
                s0 += wm[mt][0] * fmaxf(c[mt][nt][0], 0.f) + wm[mt][1] * fmaxf(c[mt][nt][2], 0.f);
                s1 += wm[mt][0] * fmaxf(c[mt][nt][1], 0.f) + wm[mt][1] * fmaxf(c[mt][nt][3], 0.f);
            }
            s0 += __shfl_xor_sync(0xffffffffu, s0, 4);
            s0 += __shfl_xor_sync(0xffffffffu, s0, 8);
            s0 += __shfl_xor_sync(0xffffffffu, s0, 16);
            s1 += __shfl_xor_sync(0xffffffffu, s1, 4);
            s1 += __shfl_xor_sync(0xffffffffu, s1, 8);
            s1 += __shfl_xor_sync(0xffffffffu, s1, 16);
            if (lane < 4) {
                float* ap = accs + (strip * BB + b) * HH + f0 + nt * 8 + 2 * tig;
                ap[0] += s0;
                ap[1] += s1;
            }
        }
        GBAR(bar);   // layer-3 act reads done before next p-build overwrites
    }

    __syncthreads();   // both groups done before cross-strip flush
    for (int idx = tid; idx < BB * HH; idx += 256) {
        float s = accs[idx] + accs[BB * HH + idx] +
                  accs[2 * BB * HH + idx] + accs[3 * BB * HH + idx];
        g_partial[blockIdx.x * (BB * HH) + idx] = s;
    }
}

// ---------------- Kernel 2: reduce + mean + relu + decoder MLP ----------------
__global__ void finalize_kernel(const float* __restrict__ D1, const float* __restrict__ c1,
                                const float* __restrict__ D2, const float* __restrict__ c2,
                                const float* __restrict__ D3, const float* __restrict__ c3,
                                float* __restrict__ out) {
    __shared__ float ha[BB * HH];
    __shared__ float hb[BB * HH];
    int tid = threadIdx.x;
    float s = 0.f;
    for (int cta = 0; cta < GRID1; cta++)
        s += g_partial[cta * (BB * HH) + tid];
    s *= (1.0f / (float)(NN * NN));
    ha[tid] = fmaxf(s, 0.f);
    __syncthreads();

    int b = tid >> 7, f = tid & 127;
    float v = c1[f];
    for (int k = 0; k < HH; k++) v += ha[b * HH + k] * D1[k * HH + f];
    hb[tid] = fmaxf(v, 0.f);
    __syncthreads();

    v = c2[f];
    for (int k = 0; k < HH; k++) v += hb[b * HH + k] * D2[k * HH + f];
    ha[tid] = fmaxf(v, 0.f);
    __syncthreads();

    if (tid < BB) {
        float o = c3[0];
        for (int k = 0; k < HH; k++) o += ha[tid * HH + k] * D3[k];
        out[tid] = o;
    }
}

// ---------------- Launch ----------------
extern "C" void kernel_launch(void* const* d_in, const int* in_sizes, int n_in,
                              void* d_out, int out_size) {
    const int*   xcat  = (const int*)d_in[0];
    const float* xfeat = (const float*)d_in[1];
    const float* emb   = (const float*)d_in[2];
    const float* W1 = (const float*)d_in[3];
    const float* b1 = (const float*)d_in[4];
    const float* W2 = (const float*)d_in[5];
    const float* b2 = (const float*)d_in[6];
    const float* W3 = (const float*)d_in[7];
    const float* b3 = (const float*)d_in[8];
    const float* D1 = (const float*)d_in[9];
    const float* c1 = (const float*)d_in[10];
    const float* D2 = (const float*)d_in[11];
    const float* c2 = (const float*)d_in[12];
    const float* D3 = (const float*)d_in[13];
    const float* c3 = (const float*)d_in[14];
    float* out = (float*)d_out;

    cudaFuncSetAttribute(pair_mlp_kernel,
                         cudaFuncAttributeMaxDynamicSharedMemorySize, SMEM_BYTES);

    build_x_kernel<<<BB * NN, DD>>>(xcat, xfeat, emb);
    pair_mlp_kernel<<<GRID1, 256, SMEM_BYTES>>>(W1, b1, W2, b2, W3, b3);
    finalize_kernel<<<1, 512>>>(D1, c1, D2, c2, D3, c3, out);
}

// round 9
// speedup vs baseline: 2.7413x; 1.0681x over previous
#include <cuda_runtime.h>
#include <cuda_fp16.h>
#include <cstdint>

// Problem constants
#define BB 4
#define NN 256
#define EE 63
#define DD 64
#define HH 128

// 16-pair chunks, exact triangular packing: 32896/16 = 2056 chunks per b.
#define CHUNKS_PER_B 2056
#define NCHUNKS (BB * CHUNKS_PER_B)     // 8224
#define GRID1 152
#define NWARPS (GRID1 * 8)              // 1216

#define APITCH 136      // fp16 elems per row (68 words: 4g+tig conflict-free)
#define W1PITCH 72      // (36 words: 4g+tig conflict-free)

// SMEM layout (bytes)
#define OFF_W1   0           // 18432
#define OFF_W2   18432       // 34816
#define OFF_W3   53248       // 34816
#define OFF_P    88064       // 128 x 136 fp16 = 34816
#define OFF_B1   122880
#define OFF_B2   123392
#define OFF_B3   123904
#define OFF_ACCS 124416      // float accs[8][BB][HH] = 16384
#define SMEM_BYTES 140800

// Scratch
__device__ float g_x[BB * NN * DD];
__device__ float g_partial[GRID1 * BB * HH];

// pack two f32 -> one fp16x2 register (rn)
__device__ __forceinline__ uint32_t pack_h2(float lo, float hi) {
    uint32_t r;
    asm("cvt.rn.f16x2.f32 %0, %1, %2;" : "=r"(r) : "f"(hi), "f"(lo));
    return r;
}

// flat triangular index p in [0, 32896) -> (i, j), j >= i
__device__ __forceinline__ int2 pair_from_flat(int p) {
    int i = (int)(256.5f - sqrtf(65792.25f - 2.0f * (float)p));
    while (i * 256 - (i * (i - 1)) / 2 > p) --i;
    while ((i + 1) * 256 - ((i + 1) * i) / 2 <= p) ++i;
    int j = i + (p - (i * 256 - (i * (i - 1)) / 2));
    return make_int2(i, j);
}

// ---------------- Kernel 0: build x = concat(emb[xcat], xfeat) ----------------
__global__ void build_x_kernel(const int* __restrict__ xcat32,
                               const float* __restrict__ xfeat,
                               const float* __restrict__ emb) {
    int row = blockIdx.x;
    int d = threadIdx.x;
    bool is64 = (xcat32[1] == 0) && (xcat32[3] == 0) && (xcat32[5] == 0) &&
                (xcat32[7] == 0) && (xcat32[9] == 0) && (xcat32[11] == 0);
    int idx = is64 ? xcat32[row * 2] : xcat32[row];
    float v = (d < EE) ? emb[idx * EE + d] : xfeat[row];
    g_x[row * DD + d] = v;
}

// ---------------- HMMA m16n8k16 fp16 (f32 accum) ----------------
__device__ __forceinline__ void mma16816(float& c0, float& c1, float& c2, float& c3,
                                         uint32_t a0, uint32_t a1, uint32_t a2, uint32_t a3,
                                         uint32_t b0, uint32_t b1) {
    asm volatile("mma.sync.aligned.m16n8k16.row.col.f32.f16.f16.f32 "
                 "{%0,%1,%2,%3}, {%4,%5,%6,%7}, {%8,%9}, {%0,%1,%2,%3};"
                 : "+f"(c0), "+f"(c1), "+f"(c2), "+f"(c3)
                 : "r"(a0), "r"(a1), "r"(a2), "r"(a3), "r"(b0), "r"(b1));
}

__device__ __forceinline__ uint32_t lds32(const void* p) { return *(const uint32_t*)p; }

// init C tiles with bias
__device__ __forceinline__ void bias_init(const float* __restrict__ bias, int tig,
                                          float C[16][4]) {
#pragma unroll
    for (int nt = 0; nt < 16; nt++) {
        float2 bv = *(const float2*)(bias + nt * 8 + 2 * tig);
        C[nt][0] = bv.x; C[nt][1] = bv.y;
        C[nt][2] = bv.x; C[nt][3] = bv.y;
    }
}

// relu + pack C (f32) -> next-layer A fragments (fp16x2)
// A-frag of m16n8k16 for k-block ks: rows (g, g+8), cols (16ks+2tig, +1, +8, +9)
// = C tiles nt=2ks (cols 16ks+2tig,+1) and nt=2ks+1 (cols +8,+9), same rows.
__device__ __forceinline__ void pack_a(const float C[16][4], uint32_t A[8][4]) {
#pragma unroll
    for (int ks = 0; ks < 8; ks++) {
        const float* e = C[2 * ks];
        const float* o = C[2 * ks + 1];
        A[ks][0] = pack_h2(fmaxf(e[0], 0.f), fmaxf(e[1], 0.f));
        A[ks][1] = pack_h2(fmaxf(e[2], 0.f), fmaxf(e[3], 0.f));
        A[ks][2] = pack_h2(fmaxf(o[0], 0.f), fmaxf(o[1], 0.f));
        A[ks][3] = pack_h2(fmaxf(o[2], 0.f), fmaxf(o[3], 0.f));
    }
}

// one K=128 layer with A in registers, B (weights) from SMEM
__device__ __forceinline__ void layer_reg(const uint32_t A[8][4],
                                          const __half* __restrict__ W,
                                          int g, int tig, float C[16][4]) {
#pragma unroll
    for (int ks = 0; ks < 8; ks++) {
        int k = ks * 16 + 2 * tig;
#pragma unroll
        for (int nt = 0; nt < 16; nt++) {
            const __half* wr = W + (nt * 8 + g) * APITCH + k;
            uint32_t b0 = lds32(wr), b1 = lds32(wr + 8);
            mma16816(C[nt][0], C[nt][1], C[nt][2], C[nt][3],
                     A[ks][0], A[ks][1], A[ks][2], A[ks][3], b0, b1);
        }
    }
}

// transpose weights into SMEM (single fp16)
__device__ void load_w(const float* __restrict__ W, int K, __half* dst, int pitch, int tid) {
    for (int idx = tid; idx < K * HH; idx += 256) {
        int f = idx & 127, k = idx >> 7;
        dst[f * pitch + k] = __float2half(W[k * HH + f]);
    }
}

// ---------------- Kernel 1: persistent fp16 pair-MLP, barrier-free warps ----------------
__global__ void __launch_bounds__(256, 1)
pair_mlp_kernel(const float* __restrict__ W1, const float* __restrict__ b1,
                const float* __restrict__ W2, const float* __restrict__ b2,
                const float* __restrict__ W3, const float* __restrict__ b3) {
    extern __shared__ char sm[];
    __half* W1s = (__half*)(sm + OFF_W1);
    __half* W2s = (__half*)(sm + OFF_W2);
    __half* W3s = (__half*)(sm + OFF_W3);
    __half* pbuf = (__half*)(sm + OFF_P);
    float* b1s = (float*)(sm + OFF_B1);
    float* b2s = (float*)(sm + OFF_B2);
    float* b3s = (float*)(sm + OFF_B3);
    float* accs = (float*)(sm + OFF_ACCS);   // [8 warps][BB][HH]

    const int tid = threadIdx.x;
    const int warp = tid >> 5, lane = tid & 31;
    const int g = lane >> 2, tig = lane & 3;
    __half* prow = pbuf + warp * 16 * APITCH;   // this warp's 16-row p region

    load_w(W1, DD, W1s, W1PITCH, tid);
    load_w(W2, HH, W2s, APITCH, tid);
    load_w(W3, HH, W3s, APITCH, tid);
    if (tid < 128) { b1s[tid] = b1[tid]; b2s[tid] = b2[tid]; b3s[tid] = b3[tid]; }
    for (int idx = tid; idx < 8 * BB * HH; idx += 256) accs[idx] = 0.f;
    __syncthreads();

    float C[16][4];
    uint32_t A[8][4];

    for (int cch = blockIdx.x * 8 + warp; cch < NCHUNKS; cch += NWARPS) {
        int b = cch / CHUNKS_PER_B;
        int r = cch - b * CHUNKS_PER_B;
        int P0 = r * 16;                        // flat pair base (16 pairs/chunk)

        // ---- build p: prow[m][k] = fp16(x[b,im,k] * x[b,jm,k]), m<16 (warp-local) ----
        __syncwarp();
        {
            int m = lane >> 1;
            int kh = (lane & 1) * 32;
            int2 ij = pair_from_flat(P0 + m);
            const float4* xi = (const float4*)(g_x + (b * NN + ij.x) * DD + kh);
            const float4* xj = (const float4*)(g_x + (b * NN + ij.y) * DD + kh);
            __half* row = prow + m * APITCH + kh;
#pragma unroll
            for (int q = 0; q < 8; q++) {
                float4 a4 = xi[q], c4 = xj[q];
                *(uint32_t*)(row + q * 4)     = pack_h2(a4.x * c4.x, a4.y * c4.y);
                *(uint32_t*)(row + q * 4 + 2) = pack_h2(a4.z * c4.z, a4.w * c4.w);
            }
        }
        __syncwarp();

        // ---- Layer 1 (K=64): A from p SMEM, C = 16 pairs x 128 feats ----
        bias_init(b1s, tig, C);
#pragma unroll
        for (int ks = 0; ks < 4; ks++) {
            int k = ks * 16 + 2 * tig;
            const __half* ar = prow + g * APITCH + k;
            uint32_t a0 = lds32(ar);
            uint32_t a1 = lds32(ar + 8 * APITCH);
            uint32_t a2 = lds32(ar + 8);
            uint32_t a3 = lds32(ar + 8 * APITCH + 8);
#pragma unroll
            for (int nt = 0; nt < 16; nt++) {
                const __half* wr = W1s + (nt * 8 + g) * W1PITCH + k;
                uint32_t b0 = lds32(wr), b1v = lds32(wr + 8);
                mma16816(C[nt][0], C[nt][1], C[nt][2], C[nt][3],
                         a0, a1, a2, a3, b0, b1v);
            }
        }

        // ---- Layer 2 (K=128): A = relu(C1) in regs ----
        pack_a(C, A);
        bias_init(b2s, tig, C);
        layer_reg(A, W2s, g, tig, C);

        // ---- Layer 3 (K=128) ----
        pack_a(C, A);
        bias_init(b3s, tig, C);
        layer_reg(A, W3s, g, tig, C);

        // ---- epilogue: relu + multiplicity + pooled reduce (warp-local) ----
        int2 ija = pair_from_flat(P0 + g);
        int2 ijb = pair_from_flat(P0 + g + 8);
        float wa = (ija.x == ija.y) ? 1.f : 2.f;
        float wb = (ijb.x == ijb.y) ? 1.f : 2.f;
        float* ap = accs + (warp * BB + b) * HH + 2 * tig;
#pragma unroll
        for (int nt = 0; nt < 16; nt++) {
            float s0 = wa * fmaxf(C[nt][0], 0.f) + wb * fmaxf(C[nt][2], 0.f);
            float s1 = wa * fmaxf(C[nt][1], 0.f) + wb * fmaxf(C[nt][3], 0.f);
            s0 += __shfl_xor_sync(0xffffffffu, s0, 4);
            s0 += __shfl_xor_sync(0xffffffffu, s0, 8);
            s0 += __shfl_xor_sync(0xffffffffu, s0, 16);
            s1 += __shfl_xor_sync(0xffffffffu, s1, 4);
            s1 += __shfl_xor_sync(0xffffffffu, s1, 8);
            s1 += __shfl_xor_sync(0xffffffffu, s1, 16);
            if (lane < 4) {
                ap[nt * 8]     += s0;
                ap[nt * 8 + 1] += s1;
            }
        }
    }

    __syncthreads();   // all warps done before cross-strip flush
    for (int idx = tid; idx < BB * HH; idx += 256) {
        float s = 0.f;
#pragma unroll
        for (int w = 0; w < 8; w++) s += accs[w * BB * HH + idx];
        g_partial[blockIdx.x * (BB * HH) + idx] = s;
    }
}

// ---------------- Kernel 2: reduce + mean + relu + decoder MLP ----------------
__global__ void finalize_kernel(const float* __restrict__ D1, const float* __restrict__ c1,
                                const float* __restrict__ D2, const float* __restrict__ c2,
                                const float* __restrict__ D3, const float* __restrict__ c3,
                                float* __restrict__ out) {
    __shared__ float ha[BB * HH];
    __shared__ float hb[BB * HH];
    int tid = threadIdx.x;
    float s = 0.f;
    for (int cta = 0; cta < GRID1; cta++)
        s += g_partial[cta * (BB * HH) + tid];
    s *= (1.0f / (float)(NN * NN));
    ha[tid] = fmaxf(s, 0.f);
    __syncthreads();

    int b = tid >> 7, f = tid & 127;
    float v = c1[f];
    for (int k = 0; k < HH; k++) v += ha[b * HH + k] * D1[k * HH + f];
    hb[tid] = fmaxf(v, 0.f);
    __syncthreads();

    v = c2[f];
    for (int k = 0; k < HH; k++) v += hb[b * HH + k] * D2[k * HH + f];
    ha[tid] = fmaxf(v, 0.f);
    __syncthreads();

    if (tid < BB) {
        float o = c3[0];
        for (int k = 0; k < HH; k++) o += ha[tid * HH + k] * D3[k];
        out[tid] = o;
    }
}

// ---------------- Launch ----------------
extern "C" void kernel_launch(void* const* d_in, const int* in_sizes, int n_in,
                              void* d_out, int out_size) {
    const int*   xcat  = (const int*)d_in[0];
    const float* xfeat = (const float*)d_in[1];
    const float* emb   = (const float*)d_in[2];
    const float* W1 = (const float*)d_in[3];
    const float* b1 = (const float*)d_in[4];
    const float* W2 = (const float*)d_in[5];
    const float* b2 = (const float*)d_in[6];
    const float* W3 = (const float*)d_in[7];
    const float* b3 = (const float*)d_in[8];
    const float* D1 = (const float*)d_in[9];
    const float* c1 = (const float*)d_in[10];
    const float* D2 = (const float*)d_in[11];
    const float* c2 = (const float*)d_in[12];
    const float* D3 = (const float*)d_in[13];
    const float* c3 = (const float*)d_in[14];
    float* out = (float*)d_out;

    cudaFuncSetAttribute(pair_mlp_kernel,
                         cudaFuncAttributeMaxDynamicSharedMemorySize, SMEM_BYTES);

    build_x_kernel<<<BB * NN, DD>>>(xcat, xfeat, emb);
    pair_mlp_kernel<<<GRID1, 256, SMEM_BYTES>>>(W1, b1, W2, b2, W3, b3);
    finalize_kernel<<<1, 512>>>(D1, c1, D2, c2, D3, c3, out);
}

// round 10
// speedup vs baseline: 2.8736x; 1.0483x over previous
#include <cuda_runtime.h>
#include <cuda_fp16.h>
#include <cstdint>

// Problem constants
#define BB 4
#define NN 256
#define EE 63
#define DD 64
#define HH 128

// 16-pair chunks, exact triangular packing: 32896/16 = 2056 chunks per b.
#define CHUNKS_PER_B 2056
#define NCHUNKS (BB * CHUNKS_PER_B)     // 8224
#define GRID1 152
#define NTHREADS 384
#define NWARPS_CTA 12
#define NWARPS (GRID1 * NWARPS_CTA)     // 1824

#define APITCH 136      // fp16 elems per row (272B = 17*16B: LDSM conflict-free)
#define W1PITCH 72      // (144B = 9*16B)

// SMEM layout (bytes)
#define OFF_W1   0           // 18432
#define OFF_W2   18432       // 34816
#define OFF_W3   53248       // 34816
#define OFF_P    88064       // 12 warps x 16 x 136 fp16 = 52224
#define OFF_B1   140288
#define OFF_B2   140800
#define OFF_B3   141312
#define OFF_ACCS 141824      // float accs[12][BB][HH] = 24576
#define SMEM_BYTES 166400

// Scratch
__device__ float g_x[BB * NN * DD];
__device__ float g_partial[GRID1 * BB * HH];

// pack two f32 -> one fp16x2 register (rn)
__device__ __forceinline__ uint32_t pack_h2(float lo, float hi) {
    uint32_t r;
    asm("cvt.rn.f16x2.f32 %0, %1, %2;" : "=r"(r) : "f"(hi), "f"(lo));
    return r;
}
// elementwise max with 0 on fp16x2
__device__ __forceinline__ uint32_t relu_h2(uint32_t v) {
    uint32_t r;
    asm("max.f16x2 %0, %1, %2;" : "=r"(r) : "r"(v), "r"(0u));
    return r;
}

__device__ __forceinline__ uint32_t smaddr(const void* p) {
    uint32_t a;
    asm("{ .reg .u64 t; cvta.to.shared.u64 t, %1; cvt.u32.u64 %0, t; }"
        : "=r"(a) : "l"(p));
    return a;
}

// ldmatrix x4 (b16): 4 8x8 matrices, per-lane row addresses
__device__ __forceinline__ void ldsm4(uint32_t r[4], uint32_t addr) {
    asm volatile("ldmatrix.sync.aligned.m8n8.x4.shared.b16 {%0,%1,%2,%3}, [%4];"
                 : "=r"(r[0]), "=r"(r[1]), "=r"(r[2]), "=r"(r[3]) : "r"(addr));
}

// flat triangular index p in [0, 32896) -> (i, j), j >= i
__device__ __forceinline__ int2 pair_from_flat(int p) {
    int i = (int)(256.5f - sqrtf(65792.25f - 2.0f * (float)p));
    while (i * 256 - (i * (i - 1)) / 2 > p) --i;
    while ((i + 1) * 256 - ((i + 1) * i) / 2 <= p) ++i;
    int j = i + (p - (i * 256 - (i * (i - 1)) / 2));
    return make_int2(i, j);
}

// ---------------- Kernel 0: build x = concat(emb[xcat], xfeat) ----------------
__global__ void build_x_kernel(const int* __restrict__ xcat32,
                               const float* __restrict__ xfeat,
                               const float* __restrict__ emb) {
    int idx = blockIdx.x * 256 + threadIdx.x;     // 65536 total
    int row = idx >> 6, d = idx & 63;
    bool is64 = (xcat32[1] == 0) && (xcat32[3] == 0) && (xcat32[5] == 0) &&
                (xcat32[7] == 0) && (xcat32[9] == 0) && (xcat32[11] == 0);
    int ci = is64 ? xcat32[row * 2] : xcat32[row];
    float v = (d < EE) ? emb[ci * EE + d] : xfeat[row];
    g_x[row * DD + d] = v;
}

// ---------------- HMMA m16n8k16 fp16 (f32 accum) ----------------
__device__ __forceinline__ void mma16816(float& c0, float& c1, float& c2, float& c3,
                                         uint32_t a0, uint32_t a1, uint32_t a2, uint32_t a3,
                                         uint32_t b0, uint32_t b1) {
    asm volatile("mma.sync.aligned.m16n8k16.row.col.f32.f16.f16.f32 "
                 "{%0,%1,%2,%3}, {%4,%5,%6,%7}, {%8,%9}, {%0,%1,%2,%3};"
                 : "+f"(c0), "+f"(c1), "+f"(c2), "+f"(c3)
                 : "r"(a0), "r"(a1), "r"(a2), "r"(a3), "r"(b0), "r"(b1));
}

// init C tiles with bias
__device__ __forceinline__ void bias_init(const float* __restrict__ bias, int tig,
                                          float C[16][4]) {
#pragma unroll
    for (int nt = 0; nt < 16; nt++) {
        float2 bv = *(const float2*)(bias + nt * 8 + 2 * tig);
        C[nt][0] = bv.x; C[nt][1] = bv.y;
        C[nt][2] = bv.x; C[nt][3] = bv.y;
    }
}

// relu + pack C (f32) -> next-layer A fragments (fp16x2)
__device__ __forceinline__ void pack_a(const float C[16][4], uint32_t A[8][4]) {
#pragma unroll
    for (int ks = 0; ks < 8; ks++) {
        const float* e = C[2 * ks];
        const float* o = C[2 * ks + 1];
        A[ks][0] = relu_h2(pack_h2(e[0], e[1]));
        A[ks][1] = relu_h2(pack_h2(e[2], e[3]));
        A[ks][2] = relu_h2(pack_h2(o[0], o[1]));
        A[ks][3] = relu_h2(pack_h2(o[2], o[3]));
    }
}

// one K=128 layer: A in regs, B via LDSM from SMEM (per-lane base addr aW)
__device__ __forceinline__ void layer_reg(const uint32_t A[8][4], uint32_t aW,
                                          float C[16][4]) {
#pragma unroll
    for (int ks = 0; ks < 8; ks++) {
#pragma unroll
        for (int ntp = 0; ntp < 8; ntp++) {
            uint32_t b[4];
            ldsm4(b, aW + (uint32_t)(ntp * 16 * APITCH + ks * 16) * 2);
            mma16816(C[2*ntp][0], C[2*ntp][1], C[2*ntp][2], C[2*ntp][3],
                     A[ks][0], A[ks][1], A[ks][2], A[ks][3], b[0], b[1]);
            mma16816(C[2*ntp+1][0], C[2*ntp+1][1], C[2*ntp+1][2], C[2*ntp+1][3],
                     A[ks][0], A[ks][1], A[ks][2], A[ks][3], b[2], b[3]);
        }
    }
}

// transpose weights into SMEM (single fp16)
__device__ void load_w(const float* __restrict__ W, int K, __half* dst, int pitch, int tid) {
    for (int idx = tid; idx < K * HH; idx += NTHREADS) {
        int f = idx & 127, k = idx >> 7;
        dst[f * pitch + k] = __float2half(W[k * HH + f]);
    }
}

// ---------------- Kernel 1: persistent fp16 pair-MLP, barrier-free warps ----------------
__global__ void __launch_bounds__(NTHREADS, 1)
pair_mlp_kernel(const float* __restrict__ W1, const float* __restrict__ b1,
                const float* __restrict__ W2, const float* __restrict__ b2,
                const float* __restrict__ W3, const float* __restrict__ b3) {
    extern __shared__ char sm[];
    __half* W1s = (__half*)(sm + OFF_W1);
    __half* W2s = (__half*)(sm + OFF_W2);
    __half* W3s = (__half*)(sm + OFF_W3);
    __half* pbuf = (__half*)(sm + OFF_P);
    float* b1s = (float*)(sm + OFF_B1);
    float* b2s = (float*)(sm + OFF_B2);
    float* b3s = (float*)(sm + OFF_B3);
    float* accs = (float*)(sm + OFF_ACCS);   // [12 warps][BB][HH]

    const int tid = threadIdx.x;
    const int warp = tid >> 5, lane = tid & 31;
    const int g = lane >> 2, tig = lane & 3;
    __half* prow = pbuf + warp * 16 * APITCH;   // this warp's 16-row p region

    load_w(W1, DD, W1s, W1PITCH, tid);
    load_w(W2, HH, W2s, APITCH, tid);
    load_w(W3, HH, W3s, APITCH, tid);
    if (tid < 128) { b1s[tid] = b1[tid]; b2s[tid] = b2[tid]; b3s[tid] = b3[tid]; }
    for (int idx = tid; idx < NWARPS_CTA * BB * HH; idx += NTHREADS) accs[idx] = 0.f;
    __syncthreads();

    // per-lane LDSM base addresses
    // B matrices: q = lane>>3: rows 8*(q>>1), k-half 8*(q&1); r = lane&7
    const int lr = lane & 7;
    const int bq_row = 8 * ((lane >> 4) & 1) + lr;
    const int bq_kh  = 8 * ((lane >> 3) & 1);
    const uint32_t aW1 = smaddr(W1s) + (uint32_t)(bq_row * W1PITCH + bq_kh) * 2;
    const uint32_t aW2 = smaddr(W2s) + (uint32_t)(bq_row * APITCH + bq_kh) * 2;
    const uint32_t aW3 = smaddr(W3s) + (uint32_t)(bq_row * APITCH + bq_kh) * 2;
    // A matrices: q = lane>>3: rows 8*(q&1), k-half 8*(q>>1)
    const int aq_row = 8 * ((lane >> 3) & 1) + lr;
    const int aq_kh  = 8 * ((lane >> 4) & 1);
    const uint32_t aP = smaddr(prow) + (uint32_t)(aq_row * APITCH + aq_kh) * 2;

    float C[16][4];
    uint32_t A[8][4];

    for (int cch = blockIdx.x * NWARPS_CTA + warp; cch < NCHUNKS; cch += NWARPS) {
        int b = cch / CHUNKS_PER_B;
        int r = cch - b * CHUNKS_PER_B;
        int P0 = r * 16;                        // flat pair base (16 pairs/chunk)

        // ---- build p: prow[m][k] = fp16(x[b,im,k] * x[b,jm,k]), m<16 (warp-local) ----
        __syncwarp();
        {
            int m = lane >> 1;
            int kh = (lane & 1) * 32;
            int2 ij = pair_from_flat(P0 + m);
            const float4* xi = (const float4*)(g_x + (b * NN + ij.x) * DD + kh);
            const float4* xj = (const float4*)(g_x + (b * NN + ij.y) * DD + kh);
            __half* row = prow + m * APITCH + kh;
#pragma unroll
            for (int q = 0; q < 8; q++) {
                float4 a4 = xi[q], c4 = xj[q];
                *(uint32_t*)(row + q * 4)     = pack_h2(a4.x * c4.x, a4.y * c4.y);
                *(uint32_t*)(row + q * 4 + 2) = pack_h2(a4.z * c4.z, a4.w * c4.w);
            }
        }
        __syncwarp();

        // ---- Layer 1 (K=64): A via LDSM from p, C = 16 pairs x 128 feats ----
        bias_init(b1s, tig, C);
#pragma unroll
        for (int ks = 0; ks < 4; ks++) {
            uint32_t a[4];
            ldsm4(a, aP + (uint32_t)(ks * 16) * 2);
#pragma unroll
            for (int ntp = 0; ntp < 8; ntp++) {
                uint32_t bfr[4];
                ldsm4(bfr, aW1 + (uint32_t)(ntp * 16 * W1PITCH + ks * 16) * 2);
                mma16816(C[2*ntp][0], C[2*ntp][1], C[2*ntp][2], C[2*ntp][3],
                         a[0], a[1], a[2], a[3], bfr[0], bfr[1]);
                mma16816(C[2*ntp+1][0], C[2*ntp+1][1], C[2*ntp+1][2], C[2*ntp+1][3],
                         a[0], a[1], a[2], a[3], bfr[2], bfr[3]);
            }
        }

        // ---- Layer 2 (K=128): A = relu(C1) in regs ----
        pack_a(C, A);
        bias_init(b2s, tig, C);
        layer_reg(A, aW2, C);

        // ---- Layer 3 (K=128) ----
        pack_a(C, A);
        bias_init(b3s, tig, C);
        layer_reg(A, aW3, C);

        // ---- epilogue: relu + multiplicity + pooled reduce (warp-local) ----
        int2 ija = pair_from_flat(P0 + g);
        int2 ijb = pair_from_flat(P0 + g + 8);
        float wa = (ija.x == ija.y) ? 1.f : 2.f;
        float wb = (ijb.x == ijb.y) ? 1.f : 2.f;
        float* ap = accs + (warp * BB + b) * HH + 2 * tig;
#pragma unroll
        for (int nt = 0; nt < 16; nt++) {
            float s0 = wa * fmaxf(C[nt][0], 0.f) + wb * fmaxf(C[nt][2], 0.f);
            float s1 = wa * fmaxf(C[nt][1], 0.f) + wb * fmaxf(C[nt][3], 0.f);
            s0 += __shfl_xor_sync(0xffffffffu, s0, 4);
            s0 += __shfl_xor_sync(0xffffffffu, s0, 8);
            s0 += __shfl_xor_sync(0xffffffffu, s0, 16);
            s1 += __shfl_xor_sync(0xffffffffu, s1, 4);
            s1 += __shfl_xor_sync(0xffffffffu, s1, 8);
            s1 += __shfl_xor_sync(0xffffffffu, s1, 16);
            if (lane < 4) {
                ap[nt * 8]     += s0;
                ap[nt * 8 + 1] += s1;
            }
        }
    }

    __syncthreads();   // all warps done before cross-strip flush
    for (int idx = tid; idx < BB * HH; idx += NTHREADS) {
        float s = 0.f;
#pragma unroll
        for (int w = 0; w < NWARPS_CTA; w++) s += accs[w * BB * HH + idx];
        g_partial[blockIdx.x * (BB * HH) + idx] = s;
    }
}

// ---------------- Kernel 2: reduce + mean + relu + decoder MLP ----------------
__global__ void finalize_kernel(const float* __restrict__ D1, const float* __restrict__ c1,
                                const float* __restrict__ D2, const float* __restrict__ c2,
                                const float* __restrict__ D3, const float* __restrict__ c3,
                                float* __restrict__ out) {
    __shared__ float ha[BB * HH];
    __shared__ float hb[BB * HH];
    int tid = threadIdx.x;
    float s = 0.f;
    for (int cta = 0; cta < GRID1; cta++)
        s += g_partial[cta * (BB * HH) + tid];
    s *= (1.0f / (float)(NN * NN));
    ha[tid] = fmaxf(s, 0.f);
    __syncthreads();

    int b = tid >> 7, f = tid & 127;
    float v = c1[f];
    for (int k = 0; k < HH; k++) v += ha[b * HH + k] * D1[k * HH + f];
    hb[tid] = fmaxf(v, 0.f);
    __syncthreads();

    v = c2[f];
    for (int k = 0; k < HH; k++) v += hb[b * HH + k] * D2[k * HH + f];
    ha[tid] = fmaxf(v, 0.f);
    __syncthreads();

    if (tid < BB) {
        float o = c3[0];
        for (int k = 0; k < HH; k++) o += ha[tid * HH + k] * D3[k];
        out[tid] = o;
    }
}

// ---------------- Launch ----------------
extern "C" void kernel_launch(void* const* d_in, const int* in_sizes, int n_in,
                              void* d_out, int out_size) {
    const int*   xcat  = (const int*)d_in[0];
    const float* xfeat = (const float*)d_in[1];
    const float* emb   = (const float*)d_in[2];
    const float* W1 = (const float*)d_in[3];
    const float* b1 = (const float*)d_in[4];
    const float* W2 = (const float*)d_in[5];
    const float* b2 = (const float*)d_in[6];
    const float* W3 = (const float*)d_in[7];
    const float* b3 = (const float*)d_in[8];
    const float* D1 = (const float*)d_in[9];
    const float* c1 = (const float*)d_in[10];
    const float* D2 = (const float*)d_in[11];
    const float* c2 = (const float*)d_in[12];
    const float* D3 = (const float*)d_in[13];
    const float* c3 = (const float*)d_in[14];
    float* out = (float*)d_out;

    cudaFuncSetAttribute(pair_mlp_kernel,
                         cudaFuncAttributeMaxDynamicSharedMemorySize, SMEM_BYTES);

    build_x_kernel<<<256, 256>>>(xcat, xfeat, emb);
    pair_mlp_kernel<<<GRID1, NTHREADS, SMEM_BYTES>>>(W1, b1, W2, b2, W3, b3);
    finalize_kernel<<<1, 512>>>(D1, c1, D2, c2, D3, c3, out);
}

// round 11
// speedup vs baseline: 3.1637x; 1.1010x over previous
#include <cuda_runtime.h>
#include <cuda_fp16.h>
#include <cstdint>

// Problem constants
#define BB 4
#define NN 256
#define EE 63
#define DD 64
#define HH 128

// 16-pair chunks, exact triangular packing: 32896/16 = 2056 chunks per b.
#define CHUNKS_PER_B 2056
#define NCHUNKS (BB * CHUNKS_PER_B)     // 8224
#define GRID1 152
#define NTHREADS 384
#define NWARPS_CTA 12
#define NWARPS (GRID1 * NWARPS_CTA)     // 1824

#define APITCH 136      // fp16 elems per row (272B = 17*16B: LDSM conflict-free)
#define W1PITCH 72      // (144B = 9*16B)

// SMEM layout (bytes)
#define OFF_W1   0           // 18432
#define OFF_W2   18432       // 34816
#define OFF_W3   53248       // 34816
#define OFF_P    88064       // 12 warps x 16 x 136 fp16 = 52224
#define OFF_B1   140288
#define OFF_B2   140800
#define OFF_B3   141312
#define OFF_ACCS 141824      // float accs[12][BB][HH] = 24576
#define SMEM_BYTES 166400

// Scratch
__device__ float g_x[BB * NN * DD];
__device__ float g_partial[GRID1 * BB * HH];

// pack two f32 -> one fp16x2 register (rn)
__device__ __forceinline__ uint32_t pack_h2(float lo, float hi) {
    uint32_t r;
    asm("cvt.rn.f16x2.f32 %0, %1, %2;" : "=r"(r) : "f"(hi), "f"(lo));
    return r;
}
// elementwise max with 0 on fp16x2
__device__ __forceinline__ uint32_t relu_h2(uint32_t v) {
    uint32_t r;
    asm("max.f16x2 %0, %1, %2;" : "=r"(r) : "r"(v), "r"(0u));
    return r;
}

__device__ __forceinline__ uint32_t smaddr(const void* p) {
    uint32_t a;
    asm("{ .reg .u64 t; cvta.to.shared.u64 t, %1; cvt.u32.u64 %0, t; }"
        : "=r"(a) : "l"(p));
    return a;
}

// ldmatrix x4 (b16): 4 8x8 matrices, per-lane row addresses
__device__ __forceinline__ void ldsm4(uint32_t r[4], uint32_t addr) {
    asm volatile("ldmatrix.sync.aligned.m8n8.x4.shared.b16 {%0,%1,%2,%3}, [%4];"
                 : "=r"(r[0]), "=r"(r[1]), "=r"(r[2]), "=r"(r[3]) : "r"(addr));
}

// flat triangular index p in [0, 32896) -> (i, j), j >= i
__device__ __forceinline__ int2 pair_from_flat(int p) {
    int i = (int)(256.5f - sqrtf(65792.25f - 2.0f * (float)p));
    while (i * 256 - (i * (i - 1)) / 2 > p) --i;
    while ((i + 1) * 256 - ((i + 1) * i) / 2 <= p) ++i;
    int j = i + (p - (i * 256 - (i * (i - 1)) / 2));
    return make_int2(i, j);
}

// ---------------- Kernel 0: build x = concat(emb[xcat], xfeat) ----------------
__global__ void build_x_kernel(const int* __restrict__ xcat32,
                               const float* __restrict__ xfeat,
                               const float* __restrict__ emb) {
    int idx = blockIdx.x * 256 + threadIdx.x;     // 65536 total
    int row = idx >> 6, d = idx & 63;
    bool is64 = (xcat32[1] == 0) && (xcat32[3] == 0) && (xcat32[5] == 0) &&
                (xcat32[7] == 0) && (xcat32[9] == 0) && (xcat32[11] == 0);
    int ci = is64 ? xcat32[row * 2] : xcat32[row];
    float v = (d < EE) ? emb[ci * EE + d] : xfeat[row];
    g_x[row * DD + d] = v;
}

// ---------------- HMMA m16n8k16 fp16 (f32 accum) ----------------
__device__ __forceinline__ void mma16816(float& c0, float& c1, float& c2, float& c3,
                                         uint32_t a0, uint32_t a1, uint32_t a2, uint32_t a3,
                                         uint32_t b0, uint32_t b1) {
    asm volatile("mma.sync.aligned.m16n8k16.row.col.f32.f16.f16.f32 "
                 "{%0,%1,%2,%3}, {%4,%5,%6,%7}, {%8,%9}, {%0,%1,%2,%3};"
                 : "+f"(c0), "+f"(c1), "+f"(c2), "+f"(c3)
                 : "r"(a0), "r"(a1), "r"(a2), "r"(a3), "r"(b0), "r"(b1));
}

// init C tiles with bias
__device__ __forceinline__ void bias_init(const float* __restrict__ bias, int tig,
                                          float C[16][4]) {
#pragma unroll
    for (int nt = 0; nt < 16; nt++) {
        float2 bv = *(const float2*)(bias + nt * 8 + 2 * tig);
        C[nt][0] = bv.x; C[nt][1] = bv.y;
        C[nt][2] = bv.x; C[nt][3] = bv.y;
    }
}

// relu + pack C (f32) -> next-layer A fragments (fp16x2)
__device__ __forceinline__ void pack_a(const float C[16][4], uint32_t A[8][4]) {
#pragma unroll
    for (int ks = 0; ks < 8; ks++) {
        const float* e = C[2 * ks];
        const float* o = C[2 * ks + 1];
        A[ks][0] = relu_h2(pack_h2(e[0], e[1]));
        A[ks][1] = relu_h2(pack_h2(e[2], e[3]));
        A[ks][2] = relu_h2(pack_h2(o[0], o[1]));
        A[ks][3] = relu_h2(pack_h2(o[2], o[3]));
    }
}

// one K=128 layer: A in regs, B via LDSM from SMEM (per-lane base addr aW)
__device__ __forceinline__ void layer_reg(const uint32_t A[8][4], uint32_t aW,
                                          float C[16][4]) {
#pragma unroll
    for (int ks = 0; ks < 8; ks++) {
#pragma unroll
        for (int ntp = 0; ntp < 8; ntp++) {
            uint32_t b[4];
            ldsm4(b, aW + (uint32_t)(ntp * 16 * APITCH + ks * 16) * 2);
            mma16816(C[2*ntp][0], C[2*ntp][1], C[2*ntp][2], C[2*ntp][3],
                     A[ks][0], A[ks][1], A[ks][2], A[ks][3], b[0], b[1]);
            mma16816(C[2*ntp+1][0], C[2*ntp+1][1], C[2*ntp+1][2], C[2*ntp+1][3],
                     A[ks][0], A[ks][1], A[ks][2], A[ks][3], b[2], b[3]);
        }
    }
}

// build the 16xDD p tile for chunk (b, P0) into prow (warp-local, no sync inside)
__device__ __forceinline__ void build_p(int b, int P0, __half* __restrict__ prow,
                                        int lane) {
    int m = lane >> 1;
    int kh = (lane & 1) * 32;
    int2 ij = pair_from_flat(P0 + m);
    const float4* xi = (const float4*)(g_x + (b * NN + ij.x) * DD + kh);
    const float4* xj = (const float4*)(g_x + (b * NN + ij.y) * DD + kh);
    __half* row = prow + m * APITCH + kh;
#pragma unroll
    for (int q = 0; q < 8; q++) {
        float4 a4 = xi[q], c4 = xj[q];
        *(uint32_t*)(row + q * 4)     = pack_h2(a4.x * c4.x, a4.y * c4.y);
        *(uint32_t*)(row + q * 4 + 2) = pack_h2(a4.z * c4.z, a4.w * c4.w);
    }
}

// flush register accumulators into smem accs (once per b segment), then zero
__device__ __forceinline__ void flush_acc(float acc[16][2], float* __restrict__ accs,
                                          int warp, int b, int lane, int tig) {
    float* ap = accs + (warp * BB + b) * HH + 2 * tig;
#pragma unroll
    for (int nt = 0; nt < 16; nt++) {
        float s0 = acc[nt][0], s1 = acc[nt][1];
        s0 += __shfl_xor_sync(0xffffffffu, s0, 4);
        s0 += __shfl_xor_sync(0xffffffffu, s0, 8);
        s0 += __shfl_xor_sync(0xffffffffu, s0, 16);
        s1 += __shfl_xor_sync(0xffffffffu, s1, 4);
        s1 += __shfl_xor_sync(0xffffffffu, s1, 8);
        s1 += __shfl_xor_sync(0xffffffffu, s1, 16);
        if (lane < 4) {
            ap[nt * 8]     += s0;
            ap[nt * 8 + 1] += s1;
        }
        acc[nt][0] = 0.f; acc[nt][1] = 0.f;
    }
}

// transpose weights into SMEM (single fp16)
__device__ void load_w(const float* __restrict__ W, int K, __half* dst, int pitch, int tid) {
    for (int idx = tid; idx < K * HH; idx += NTHREADS) {
        int f = idx & 127, k = idx >> 7;
        dst[f * pitch + k] = __float2half(W[k * HH + f]);
    }
}

// ---------------- Kernel 1: persistent fp16 pair-MLP ----------------
__global__ void __launch_bounds__(NTHREADS, 1)
pair_mlp_kernel(const float* __restrict__ W1, const float* __restrict__ b1,
                const float* __restrict__ W2, const float* __restrict__ b2,
                const float* __restrict__ W3, const float* __restrict__ b3) {
    extern __shared__ char sm[];
    __half* W1s = (__half*)(sm + OFF_W1);
    __half* W2s = (__half*)(sm + OFF_W2);
    __half* W3s = (__half*)(sm + OFF_W3);
    __half* pbuf = (__half*)(sm + OFF_P);
    float* b1s = (float*)(sm + OFF_B1);
    float* b2s = (float*)(sm + OFF_B2);
    float* b3s = (float*)(sm + OFF_B3);
    float* accs = (float*)(sm + OFF_ACCS);   // [12 warps][BB][HH]

    const int tid = threadIdx.x;
    const int warp = tid >> 5, lane = tid & 31;
    const int g = lane >> 2, tig = lane & 3;
    __half* prow = pbuf + warp * 16 * APITCH;   // this warp's 16-row p region

    load_w(W1, DD, W1s, W1PITCH, tid);
    load_w(W2, HH, W2s, APITCH, tid);
    load_w(W3, HH, W3s, APITCH, tid);
    if (tid < 128) { b1s[tid] = b1[tid]; b2s[tid] = b2[tid]; b3s[tid] = b3[tid]; }
    for (int idx = tid; idx < NWARPS_CTA * BB * HH; idx += NTHREADS) accs[idx] = 0.f;
    __syncthreads();

    // per-lane LDSM base addresses
    const int lr = lane & 7;
    const int bq_row = 8 * ((lane >> 4) & 1) + lr;
    const int bq_kh  = 8 * ((lane >> 3) & 1);
    const uint32_t aW1 = smaddr(W1s) + (uint32_t)(bq_row * W1PITCH + bq_kh) * 2;
    const uint32_t aW2 = smaddr(W2s) + (uint32_t)(bq_row * APITCH + bq_kh) * 2;
    const uint32_t aW3 = smaddr(W3s) + (uint32_t)(bq_row * APITCH + bq_kh) * 2;
    const int aq_row = 8 * ((lane >> 3) & 1) + lr;
    const int aq_kh  = 8 * ((lane >> 4) & 1);
    const uint32_t aP = smaddr(prow) + (uint32_t)(aq_row * APITCH + aq_kh) * 2;

    // contiguous chunk range for this warp (b changes at most once)
    const int W = blockIdx.x * NWARPS_CTA + warp;
    const int cstart = (int)(((long long)W * NCHUNKS) / NWARPS);
    const int cend   = (int)(((long long)(W + 1) * NCHUNKS) / NWARPS);

    float C[16][4];
    uint32_t A[8][4];
    float acc[16][2];
#pragma unroll
    for (int nt = 0; nt < 16; nt++) { acc[nt][0] = 0.f; acc[nt][1] = 0.f; }

    int cur_b = cstart / CHUNKS_PER_B;
    // prologue: build p for the first chunk
    build_p(cur_b, (cstart - cur_b * CHUNKS_PER_B) * 16, prow, lane);

    for (int c = cstart; c < cend; c++) {
        int b = c / CHUNKS_PER_B;
        int P0 = (c - b * CHUNKS_PER_B) * 16;
        if (b != cur_b) {
            flush_acc(acc, accs, warp, cur_b, lane, tig);
            cur_b = b;
        }
        __syncwarp();

        // ---- Layer 1 (K=64): A via LDSM from prow ----
        bias_init(b1s, tig, C);
#pragma unroll
        for (int ks = 0; ks < 4; ks++) {
            uint32_t a[4];
            ldsm4(a, aP + (uint32_t)(ks * 16) * 2);
#pragma unroll
            for (int ntp = 0; ntp < 8; ntp++) {
                uint32_t bfr[4];
                ldsm4(bfr, aW1 + (uint32_t)(ntp * 16 * W1PITCH + ks * 16) * 2);
                mma16816(C[2*ntp][0], C[2*ntp][1], C[2*ntp][2], C[2*ntp][3],
                         a[0], a[1], a[2], a[3], bfr[0], bfr[1]);
                mma16816(C[2*ntp+1][0], C[2*ntp+1][1], C[2*ntp+1][2], C[2*ntp+1][3],
                         a[0], a[1], a[2], a[3], bfr[2], bfr[3]);
            }
        }

        // ---- Layer 2 prep; then prefetch-build next chunk's p tile ----
        pack_a(C, A);
        if (c + 1 < cend) {
            int b2x = (c + 1) / CHUNKS_PER_B;
            build_p(b2x, ((c + 1) - b2x * CHUNKS_PER_B) * 16, prow, lane);
        }
        bias_init(b2s, tig, C);
        layer_reg(A, aW2, C);

        // ---- Layer 3 ----
        pack_a(C, A);
        bias_init(b3s, tig, C);
        layer_reg(A, aW3, C);

        // ---- weighted accumulate into register pool (no shuffles) ----
        int2 ija = pair_from_flat(P0 + g);
        int2 ijb = pair_from_flat(P0 + g + 8);
        float wa = (ija.x == ija.y) ? 1.f : 2.f;
        float wb = (ijb.x == ijb.y) ? 1.f : 2.f;
#pragma unroll
        for (int nt = 0; nt < 16; nt++) {
            acc[nt][0] += wa * fmaxf(C[nt][0], 0.f) + wb * fmaxf(C[nt][2], 0.f);
            acc[nt][1] += wa * fmaxf(C[nt][1], 0.f) + wb * fmaxf(C[nt][3], 0.f);
        }
    }
    flush_acc(acc, accs, warp, cur_b, lane, tig);

    __syncthreads();   // all warps done before cross-strip flush
    for (int idx = tid; idx < BB * HH; idx += NTHREADS) {
        float s = 0.f;
#pragma unroll
        for (int w = 0; w < NWARPS_CTA; w++) s += accs[w * BB * HH + idx];
        g_partial[blockIdx.x * (BB * HH) + idx] = s;
    }
}

// ---------------- Kernel 2: reduce + mean + relu + decoder MLP ----------------
__global__ void finalize_kernel(const float* __restrict__ D1, const float* __restrict__ c1,
                                const float* __restrict__ D2, const float* __restrict__ c2,
                                const float* __restrict__ D3, const float* __restrict__ c3,
                                float* __restrict__ out) {
    __shared__ float ha[BB * HH];
    __shared__ float hb[BB * HH];
    int tid = threadIdx.x;
    float s = 0.f;
    for (int cta = 0; cta < GRID1; cta++)
        s += g_partial[cta * (BB * HH) + tid];
    s *= (1.0f / (float)(NN * NN));
    ha[tid] = fmaxf(s, 0.f);
    __syncthreads();

    int b = tid >> 7, f = tid & 127;
    float v = c1[f];
    for (int k = 0; k < HH; k++) v += ha[b * HH + k] * D1[k * HH + f];
    hb[tid] = fmaxf(v, 0.f);
    __syncthreads();

    v = c2[f];
    for (int k = 0; k < HH; k++) v += hb[b * HH + k] * D2[k * HH + f];
    ha[tid] = fmaxf(v, 0.f);
    __syncthreads();

    if (tid < BB) {
        float o = c3[0];
        for (int k = 0; k < HH; k++) o += ha[tid * HH + k] * D3[k];
        out[tid] = o;
    }
}

// ---------------- Launch ----------------
extern "C" void kernel_launch(void* const* d_in, const int* in_sizes, int n_in,
                              void* d_out, int out_size) {
    const int*   xcat  = (const int*)d_in[0];
    const float* xfeat = (const float*)d_in[1];
    const float* emb   = (const float*)d_in[2];
    const float* W1 = (const float*)d_in[3];
    const float* b1 = (const float*)d_in[4];
    const float* W2 = (const float*)d_in[5];
    const float* b2 = (const float*)d_in[6];
    const float* W3 = (const float*)d_in[7];
    const float* b3 = (const float*)d_in[8];
    const float* D1 = (const float*)d_in[9];
    const float* c1 = (const float*)d_in[10];
    const float* D2 = (const float*)d_in[11];
    const float* c2 = (const float*)d_in[12];
    const float* D3 = (const float*)d_in[13];
    const float* c3 = (const float*)d_in[14];
    float* out = (float*)d_out;

    cudaFuncSetAttribute(pair_mlp_kernel,
                         cudaFuncAttributeMaxDynamicSharedMemorySize, SMEM_BYTES);

    build_x_kernel<<<256, 256>>>(xcat, xfeat, emb);
    pair_mlp_kernel<<<GRID1, NTHREADS, SMEM_BYTES>>>(W1, b1, W2, b2, W3, b3);
    finalize_kernel<<<1, 512>>>(D1, c1, D2, c2, D3, c3, out);
}

// round 12
// speedup vs baseline: 3.6107x; 1.1413x over previous
#include <cuda_runtime.h>
#include <cuda_fp16.h>
#include <cstdint>

// Problem constants
#define BB 4
#define NN 256
#define EE 63
#define DD 64
#define HH 128

// 16-pair chunks per b: 32896/16 = 2056. CTAs per b: 38 (152/4).
#define CHUNKS_PER_B 2056
#define GRID1 152
#define CTAS_PER_B 38
#define NTHREADS 384
#define NWARPS_CTA 12
#define WARPS_PER_B (CTAS_PER_B * NWARPS_CTA)   // 456

#define APITCH 136      // fp16 elems per row (272B = 17*16B: LDSM conflict-free)
#define W1PITCH 72      // (144B = 9*16B)

// SMEM layout (bytes)
#define OFF_W1   0           // 18432
#define OFF_W2   18432       // 34816 -> 53248
#define OFF_W3   53248       // 34816 -> 88064
#define OFF_P    88064       // 12*16*136*2 = 52224 -> 140288  (reused as ha/hb in finalize)
#define OFF_XS   140288      // 256*64*2 = 32768 -> 173056
#define OFF_B1   173056
#define OFF_B2   173568
#define OFF_B3   174080
#define OFF_ACCS 174592      // float accs[12][HH] = 6144 -> 180736
#define SMEM_BYTES 180736

// Scratch
__device__ float g_partial[GRID1 * HH];
__device__ unsigned int g_done = 0;

// ---------------- small helpers ----------------
__device__ __forceinline__ uint32_t pack_h2(float lo, float hi) {
    uint32_t r;
    asm("cvt.rn.f16x2.f32 %0, %1, %2;" : "=r"(r) : "f"(hi), "f"(lo));
    return r;
}
__device__ __forceinline__ uint32_t relu_h2(uint32_t v) {
    uint32_t r;
    asm("max.f16x2 %0, %1, %2;" : "=r"(r) : "r"(v), "r"(0u));
    return r;
}
__device__ __forceinline__ uint32_t mul_h2(uint32_t a, uint32_t b) {
    uint32_t r;
    asm("mul.rn.f16x2 %0, %1, %2;" : "=r"(r) : "r"(a), "r"(b));
    return r;
}
__device__ __forceinline__ uint32_t smaddr(const void* p) {
    uint32_t a;
    asm("{ .reg .u64 t; cvta.to.shared.u64 t, %1; cvt.u32.u64 %0, t; }"
        : "=r"(a) : "l"(p));
    return a;
}
__device__ __forceinline__ void ldsm4(uint32_t r[4], uint32_t addr) {
    asm volatile("ldmatrix.sync.aligned.m8n8.x4.shared.b16 {%0,%1,%2,%3}, [%4];"
                 : "=r"(r[0]), "=r"(r[1]), "=r"(r[2]), "=r"(r[3]) : "r"(addr));
}

// flat triangular index p in [0, 32896) -> (i, j), j >= i
__device__ __forceinline__ int2 pair_from_flat(int p) {
    int i = (int)(256.5f - sqrtf(65792.25f - 2.0f * (float)p));
    while (i * 256 - (i * (i - 1)) / 2 > p) --i;
    while ((i + 1) * 256 - ((i + 1) * i) / 2 <= p) ++i;
    int j = i + (p - (i * 256 - (i * (i - 1)) / 2));
    return make_int2(i, j);
}

// ---------------- HMMA m16n8k16 fp16 (f32 accum) ----------------
__device__ __forceinline__ void mma16816(float& c0, float& c1, float& c2, float& c3,
                                         uint32_t a0, uint32_t a1, uint32_t a2, uint32_t a3,
                                         uint32_t b0, uint32_t b1) {
    asm volatile("mma.sync.aligned.m16n8k16.row.col.f32.f16.f16.f32 "
                 "{%0,%1,%2,%3}, {%4,%5,%6,%7}, {%8,%9}, {%0,%1,%2,%3};"
                 : "+f"(c0), "+f"(c1), "+f"(c2), "+f"(c3)
                 : "r"(a0), "r"(a1), "r"(a2), "r"(a3), "r"(b0), "r"(b1));
}

__device__ __forceinline__ void bias_init(const float* __restrict__ bias, int tig,
                                          float C[16][4]) {
#pragma unroll
    for (int nt = 0; nt < 16; nt++) {
        float2 bv = *(const float2*)(bias + nt * 8 + 2 * tig);
        C[nt][0] = bv.x; C[nt][1] = bv.y;
        C[nt][2] = bv.x; C[nt][3] = bv.y;
    }
}

__device__ __forceinline__ void pack_a(const float C[16][4], uint32_t A[8][4]) {
#pragma unroll
    for (int ks = 0; ks < 8; ks++) {
        const float* e = C[2 * ks];
        const float* o = C[2 * ks + 1];
        A[ks][0] = relu_h2(pack_h2(e[0], e[1]));
        A[ks][1] = relu_h2(pack_h2(e[2], e[3]));
        A[ks][2] = relu_h2(pack_h2(o[0], o[1]));
        A[ks][3] = relu_h2(pack_h2(o[2], o[3]));
    }
}

__device__ __forceinline__ void layer_reg(const uint32_t A[8][4], uint32_t aW,
                                          float C[16][4]) {
#pragma unroll
    for (int ks = 0; ks < 8; ks++) {
#pragma unroll
        for (int ntp = 0; ntp < 8; ntp++) {
            uint32_t b[4];
            ldsm4(b, aW + (uint32_t)(ntp * 16 * APITCH + ks * 16) * 2);
            mma16816(C[2*ntp][0], C[2*ntp][1], C[2*ntp][2], C[2*ntp][3],
                     A[ks][0], A[ks][1], A[ks][2], A[ks][3], b[0], b[1]);
            mma16816(C[2*ntp+1][0], C[2*ntp+1][1], C[2*ntp+1][2], C[2*ntp+1][3],
                     A[ks][0], A[ks][1], A[ks][2], A[ks][3], b[2], b[3]);
        }
    }
}

// build the 16xDD p tile from SMEM-resident x slice (fp16): 4 LDS.128 + 4 mul + 4 STS.128
__device__ __forceinline__ void build_p(const __half* __restrict__ xs, int P0,
                                        __half* __restrict__ prow, int lane) {
    int m = lane >> 1;
    int kh = (lane & 1) * 32;
    int2 ij = pair_from_flat(P0 + m);
    const uint4* xi = (const uint4*)(xs + ij.x * DD + kh);
    const uint4* xj = (const uint4*)(xs + ij.y * DD + kh);
    uint4* row = (uint4*)(prow + m * APITCH + kh);
#pragma unroll
    for (int q = 0; q < 4; q++) {
        uint4 a = xi[q], c = xj[q];
        uint4 r;
        r.x = mul_h2(a.x, c.x); r.y = mul_h2(a.y, c.y);
        r.z = mul_h2(a.z, c.z); r.w = mul_h2(a.w, c.w);
        row[q] = r;
    }
}

__device__ __forceinline__ void flush_acc(float acc[16][2], float* __restrict__ accs,
                                          int warp, int lane, int tig) {
    float* ap = accs + warp * HH + 2 * tig;
#pragma unroll
    for (int nt = 0; nt < 16; nt++) {
        float s0 = acc[nt][0], s1 = acc[nt][1];
        s0 += __shfl_xor_sync(0xffffffffu, s0, 4);
        s0 += __shfl_xor_sync(0xffffffffu, s0, 8);
        s0 += __shfl_xor_sync(0xffffffffu, s0, 16);
        s1 += __shfl_xor_sync(0xffffffffu, s1, 4);
        s1 += __shfl_xor_sync(0xffffffffu, s1, 8);
        s1 += __shfl_xor_sync(0xffffffffu, s1, 16);
        if (lane < 4) {
            ap[nt * 8]     = s0;
            ap[nt * 8 + 1] = s1;
        }
    }
}

__device__ void load_w(const float* __restrict__ W, int K, __half* dst, int pitch, int tid) {
    for (int idx = tid; idx < K * HH; idx += NTHREADS) {
        int f = idx & 127, k = idx >> 7;
        dst[f * pitch + k] = __float2half(W[k * HH + f]);
    }
}

// ---------------- The single fused kernel ----------------
__global__ void __launch_bounds__(NTHREADS, 1)
pair_mlp_kernel(const int* __restrict__ xcat32, const float* __restrict__ xfeat,
                const float* __restrict__ emb,
                const float* __restrict__ W1, const float* __restrict__ b1,
                const float* __restrict__ W2, const float* __restrict__ b2,
                const float* __restrict__ W3, const float* __restrict__ b3,
                const float* __restrict__ D1, const float* __restrict__ c1,
                const float* __restrict__ D2, const float* __restrict__ c2,
                const float* __restrict__ D3, const float* __restrict__ c3,
                float* __restrict__ out) {
    extern __shared__ char sm[];
    __half* W1s = (__half*)(sm + OFF_W1);
    __half* W2s = (__half*)(sm + OFF_W2);
    __half* W3s = (__half*)(sm + OFF_W3);
    __half* pbuf = (__half*)(sm + OFF_P);
    __half* xs  = (__half*)(sm + OFF_XS);
    float* b1s = (float*)(sm + OFF_B1);
    float* b2s = (float*)(sm + OFF_B2);
    float* b3s = (float*)(sm + OFF_B3);
    float* accs = (float*)(sm + OFF_ACCS);   // [12 warps][HH]
    __shared__ unsigned s_last;

    const int tid = threadIdx.x;
    const int warp = tid >> 5, lane = tid & 31;
    const int g = lane >> 2, tig = lane & 3;
    const int myb = blockIdx.x / CTAS_PER_B;          // this CTA's batch
    const int cidx = blockIdx.x - myb * CTAS_PER_B;   // CTA index within b
    __half* prow = pbuf + warp * 16 * APITCH;

    // ---- prologue: weights + x slice for this b into SMEM ----
    load_w(W1, DD, W1s, W1PITCH, tid);
    load_w(W2, HH, W2s, APITCH, tid);
    load_w(W3, HH, W3s, APITCH, tid);
    if (tid < 128) { b1s[tid] = b1[tid]; b2s[tid] = b2[tid]; b3s[tid] = b3[tid]; }
    {
        bool is64 = (xcat32[1] == 0) && (xcat32[3] == 0) && (xcat32[5] == 0) &&
                    (xcat32[7] == 0) && (xcat32[9] == 0) && (xcat32[11] == 0);
        for (int idx = tid; idx < NN * DD; idx += NTHREADS) {
            int row = idx >> 6, d = idx & 63;
            int grow = myb * NN + row;
            int ci = is64 ? xcat32[grow * 2] : xcat32[grow];
            float v = (d < EE) ? emb[ci * EE + d] : xfeat[grow];
            xs[idx] = __float2half(v);
        }
    }
    __syncthreads();

    // per-lane LDSM base addresses
    const int lr = lane & 7;
    const int bq_row = 8 * ((lane >> 4) & 1) + lr;
    const int bq_kh  = 8 * ((lane >> 3) & 1);
    const uint32_t aW1 = smaddr(W1s) + (uint32_t)(bq_row * W1PITCH + bq_kh) * 2;
    const uint32_t aW2 = smaddr(W2s) + (uint32_t)(bq_row * APITCH + bq_kh) * 2;
    const uint32_t aW3 = smaddr(W3s) + (uint32_t)(bq_row * APITCH + bq_kh) * 2;
    const int aq_row = 8 * ((lane >> 3) & 1) + lr;
    const int aq_kh  = 8 * ((lane >> 4) & 1);
    const uint32_t aP = smaddr(prow) + (uint32_t)(aq_row * APITCH + aq_kh) * 2;

    // contiguous chunk range within this b for this warp
    const int wb = cidx * NWARPS_CTA + warp;
    const int cstart = (int)(((long long)wb * CHUNKS_PER_B) / WARPS_PER_B);
    const int cend   = (int)(((long long)(wb + 1) * CHUNKS_PER_B) / WARPS_PER_B);

    float C[16][4];
    uint32_t A[8][4];
    float acc[16][2];
#pragma unroll
    for (int nt = 0; nt < 16; nt++) { acc[nt][0] = 0.f; acc[nt][1] = 0.f; }

    build_p(xs, cstart * 16, prow, lane);

    for (int c = cstart; c < cend; c++) {
        int P0 = c * 16;
        __syncwarp();

        // ---- Layer 1 (K=64) ----
        bias_init(b1s, tig, C);
#pragma unroll
        for (int ks = 0; ks < 4; ks++) {
            uint32_t a[4];
            ldsm4(a, aP + (uint32_t)(ks * 16) * 2);
#pragma unroll
            for (int ntp = 0; ntp < 8; ntp++) {
                uint32_t bfr[4];
                ldsm4(bfr, aW1 + (uint32_t)(ntp * 16 * W1PITCH + ks * 16) * 2);
                mma16816(C[2*ntp][0], C[2*ntp][1], C[2*ntp][2], C[2*ntp][3],
                         a[0], a[1], a[2], a[3], bfr[0], bfr[1]);
                mma16816(C[2*ntp+1][0], C[2*ntp+1][1], C[2*ntp+1][2], C[2*ntp+1][3],
                         a[0], a[1], a[2], a[3], bfr[2], bfr[3]);
            }
        }

        // ---- Layer 2 prep; prefetch-build next chunk's p tile ----
        pack_a(C, A);
        if (c + 1 < cend) build_p(xs, (c + 1) * 16, prow, lane);
        bias_init(b2s, tig, C);
        layer_reg(A, aW2, C);

        // ---- Layer 3 ----
        pack_a(C, A);
        bias_init(b3s, tig, C);
        layer_reg(A, aW3, C);

        // ---- weighted accumulate into register pool ----
        int2 ija = pair_from_flat(P0 + g);
        int2 ijb = pair_from_flat(P0 + g + 8);
        float wa = (ija.x == ija.y) ? 1.f : 2.f;
        float wb2 = (ijb.x == ijb.y) ? 1.f : 2.f;
#pragma unroll
        for (int nt = 0; nt < 16; nt++) {
            acc[nt][0] += wa * fmaxf(C[nt][0], 0.f) + wb2 * fmaxf(C[nt][2], 0.f);
            acc[nt][1] += wa * fmaxf(C[nt][1], 0.f) + wb2 * fmaxf(C[nt][3], 0.f);
        }
    }
    flush_acc(acc, accs, warp, lane, tig);

    __syncthreads();
    for (int idx = tid; idx < HH; idx += NTHREADS) {
        float s = 0.f;
#pragma unroll
        for (int w = 0; w < NWARPS_CTA; w++) s += accs[w * HH + idx];
        g_partial[blockIdx.x * HH + idx] = s;
    }

    // ---- last-CTA finalize (deterministic: fixed-order reduction) ----
    __threadfence();
    if (tid == 0) {
        unsigned old = atomicAdd(&g_done, 1u);
        s_last = (old == GRID1 - 1) ? 1u : 0u;
    }
    __syncthreads();
    if (!s_last) return;
    __threadfence();

    float* ha = (float*)(sm + OFF_P);        // [BB*HH]
    float* hb = ha + BB * HH;
    for (int idx = tid; idx < BB * HH; idx += NTHREADS) {
        int b = idx >> 7, f = idx & 127;
        float s = 0.f;
        for (int cc = 0; cc < CTAS_PER_B; cc++)
            s += g_partial[(b * CTAS_PER_B + cc) * HH + f];
        ha[idx] = fmaxf(s * (1.0f / (float)(NN * NN)), 0.f);
    }
    __syncthreads();
    for (int idx = tid; idx < BB * HH; idx += NTHREADS) {
        int b = idx >> 7, f = idx & 127;
        float v = c1[f];
        for (int k = 0; k < HH; k++) v += ha[b * HH + k] * D1[k * HH + f];
        hb[idx] = fmaxf(v, 0.f);
    }
    __syncthreads();
    for (int idx = tid; idx < BB * HH; idx += NTHREADS) {
        int b = idx >> 7, f = idx & 127;
        float v = c2[f];
        for (int k = 0; k < HH; k++) v += hb[b * HH + k] * D2[k * HH + f];
        ha[idx] = fmaxf(v, 0.f);
    }
    __syncthreads();
    if (tid < BB) {
        float o = c3[0];
        for (int k = 0; k < HH; k++) o += ha[tid * HH + k] * D3[k];
        out[tid] = o;
    }
    if (tid == 0) g_done = 0;    // reset for next graph replay
}

// ---------------- Launch ----------------
extern "C" void kernel_launch(void* const* d_in, const int* in_sizes, int n_in,
                              void* d_out, int out_size) {
    const int*   xcat  = (const int*)d_in[0];
    const float* xfeat = (const float*)d_in[1];
    const float* emb   = (const float*)d_in[2];
    const float* W1 = (const float*)d_in[3];
    const float* b1 = (const float*)d_in[4];
    const float* W2 = (const float*)d_in[5];
    const float* b2 = (const float*)d_in[6];
    const float* W3 = (const float*)d_in[7];
    const float* b3 = (const float*)d_in[8];
    const float* D1 = (const float*)d_in[9];
    const float* c1 = (const float*)d_in[10];
    const float* D2 = (const float*)d_in[11];
    const float* c2 = (const float*)d_in[12];
    const float* D3 = (const float*)d_in[13];
    const float* c3 = (const float*)d_in[14];
    float* out = (float*)d_out;

    cudaFuncSetAttribute(pair_mlp_kernel,
                         cudaFuncAttributeMaxDynamicSharedMemorySize, SMEM_BYTES);

    pair_mlp_kernel<<<GRID1, NTHREADS, SMEM_BYTES>>>(
        xcat, xfeat, emb, W1, b1, W2, b2, W3, b3,
        D1, c1, D2, c2, D3, c3, out);
}